// round 9
// baseline (speedup 1.0000x reference)
#include <cuda_runtime.h>
#include <cuda_bf16.h>
#include <cstdint>

// Problem-size constants (fixed by the dataset)
#define NUc 200000
#define NMc 80000
#define Ec  2000000
#define ELc 500000
#define Hc  128
#define FDc 512

// ---------------- scratch (static device allocations; no cudaMalloc) ----------------
__device__ float g_movie_x[NMc * Hc];   // movie_x; later reused as movie_o
__device__ float g_movie_h[NMc * Hc];
__device__ float g_aggM  [NMc * Hc];
__device__ float g_user_h[NUc * Hc];
__device__ float g_user_o[NUc * Hc];
__device__ float g_aggU2 [NUc * Hc];    // conv2 user aggregation

__device__ int g_cnt_m[NMc];
__device__ int g_cnt_u[NUc];
__device__ int g_off_m[NMc + 1];
__device__ int g_off_u[NUc + 1];
__device__ int g_pos_m[NMc];
__device__ int g_pos_u[NUc];
__device__ int g_adj_m[Ec];             // user ids grouped by movie
__device__ int g_adj_u[Ec];             // movie ids grouped by user
__device__ int g_bsum_m[256];
__device__ int g_bsum_u[256];
__device__ float g_cvec[Hc];            // u0 @ Wl1_um
__device__ float g_bvec_u1[Hc];         // bl1_mu + u0 @ Wr1_mu

// bf16 hi/lo weight pool: [hi K*128][lo K*128] per matrix
#define OFF_WM     0
#define OFF_WL1MU  131072
#define OFF_WR1UM  163840
#define OFF_WL2UM  196608
#define OFF_WR2UM  229376
#define OFF_WL2MU  262144
#define OFF_WR2MU  294912
__device__ __nv_bfloat16 g_wpool[327680];

// ---------------- host-side stream/event resources (created pre-main) ----------------
struct StreamRes {
    cudaStream_t s1;
    cudaEvent_t eFork, eHist, eCsr, eG1, eMH, eUH, eMO;
    StreamRes() {
        cudaStreamCreateWithFlags(&s1, cudaStreamNonBlocking);
        cudaEventCreateWithFlags(&eFork, cudaEventDisableTiming);
        cudaEventCreateWithFlags(&eHist, cudaEventDisableTiming);
        cudaEventCreateWithFlags(&eCsr,  cudaEventDisableTiming);
        cudaEventCreateWithFlags(&eG1,   cudaEventDisableTiming);
        cudaEventCreateWithFlags(&eMH,   cudaEventDisableTiming);
        cudaEventCreateWithFlags(&eUH,   cudaEventDisableTiming);
        cudaEventCreateWithFlags(&eMO,   cudaEventDisableTiming);
    }
};
static StreamRes g_sr;

// ---------------- small utility kernels ----------------
__global__ void zero_int_kernel(int* p, int n) {
    int i = blockIdx.x * blockDim.x + threadIdx.x;
    if (i < n) p[i] = 0;
}
__global__ void copy_int_kernel(int* dst, const int* src, int n) {
    int i = blockIdx.x * blockDim.x + threadIdx.x;
    if (i < n) dst[i] = src[i];
}
__global__ void hist_kernel(const int* __restrict__ src, const int* __restrict__ dst,
                            int* cnt_u, int* cnt_m, int n) {
    for (int e = blockIdx.x * blockDim.x + threadIdx.x; e < n; e += gridDim.x * blockDim.x) {
        atomicAdd(&cnt_m[dst[e]], 1);
        atomicAdd(&cnt_u[src[e]], 1);
    }
}
__global__ void place_kernel(const int* __restrict__ src, const int* __restrict__ dst,
                             int* pos_u, int* pos_m, int* adj_u, int* adj_m, int n) {
    for (int e = blockIdx.x * blockDim.x + threadIdx.x; e < n; e += gridDim.x * blockDim.x) {
        int s = src[e], d = dst[e];
        int p = atomicAdd(&pos_m[d], 1);
        adj_m[p] = s;
        int q = atomicAdd(&pos_u[s], 1);
        adj_u[q] = d;
    }
}
__global__ void scan_block_kernel(const int* __restrict__ cnt, int* out, int* bsums, int n) {
    __shared__ int sh[1024];
    int tid = threadIdx.x;
    int i = blockIdx.x * 1024 + tid;
    int v = (i < n) ? cnt[i] : 0;
    sh[tid] = v;
    __syncthreads();
    #pragma unroll
    for (int off = 1; off < 1024; off <<= 1) {
        int t = (tid >= off) ? sh[tid - off] : 0;
        __syncthreads();
        sh[tid] += t;
        __syncthreads();
    }
    if (i < n) out[i + 1] = sh[tid];
    if (tid == 1023) bsums[blockIdx.x] = sh[1023];
}
__global__ void scan_sums_kernel(int* bsums, int nb) {
    if (threadIdx.x == 0 && blockIdx.x == 0) {
        int acc = 0;
        for (int b = 0; b < nb; b++) { int v = bsums[b]; bsums[b] = acc; acc += v; }
    }
}
__global__ void scan_add_kernel(int* out, const int* __restrict__ bsums, int n) {
    int i = blockIdx.x * 1024 + threadIdx.x;
    if (i < n) out[i + 1] += bsums[blockIdx.x];
    if (i == 0) out[0] = 0;
}
__global__ void prevec_kernel(const float* __restrict__ u0,
                              const float* __restrict__ Wl1um,
                              const float* __restrict__ Wr1mu,
                              const float* __restrict__ bl1mu,
                              float* cvec, float* bvec) {
    int j = threadIdx.x;
    float c = 0.f, r = 0.f;
    for (int k = 0; k < Hc; k++) {
        float u = u0[k];
        c += u * Wl1um[k * Hc + j];
        r += u * Wr1mu[k * Hc + j];
    }
    cvec[j] = c;
    bvec[j] = bl1mu[j] + r;
}

__device__ __forceinline__ float bf_rn(float v) {
    return __bfloat162float(__float2bfloat16_rn(v));
}
// weight pre-conversion: out[0..n) = hi(bf16), out[n..2n) = lo(bf16)
__global__ void wconv_kernel(const float* __restrict__ W, __nv_bfloat16* out, int n) {
    int i = blockIdx.x * blockDim.x + threadIdx.x;
    if (i < n) {
        float w = W[i];
        float h = bf_rn(w);
        out[i] = __float2bfloat16_rn(h);
        out[n + i] = __float2bfloat16_rn(w - h);
    }
}

// ---------------- scatter-mean via CSR gather: one warp per destination node ----------------
__global__ void agg_mean_kernel(const int* __restrict__ off, const int* __restrict__ adj,
                                const float* __restrict__ X, float* __restrict__ out, int n) {
    int w = (blockIdx.x * blockDim.x + threadIdx.x) >> 5;
    int lane = threadIdx.x & 31;
    if (w >= n) return;
    int s = off[w], e = off[w + 1];
    float4 acc = make_float4(0.f, 0.f, 0.f, 0.f);
    int i = s;
    for (; i + 1 < e; i += 2) {
        int j0 = adj[i], j1 = adj[i + 1];
        float4 v0 = *(const float4*)(X + (size_t)j0 * Hc + lane * 4);
        float4 v1 = *(const float4*)(X + (size_t)j1 * Hc + lane * 4);
        acc.x += v0.x + v1.x; acc.y += v0.y + v1.y;
        acc.z += v0.z + v1.z; acc.w += v0.w + v1.w;
    }
    if (i < e) {
        int j = adj[i];
        float4 v = *(const float4*)(X + (size_t)j * Hc + lane * 4);
        acc.x += v.x; acc.y += v.y; acc.z += v.z; acc.w += v.w;
    }
    int cnt = e - s;
    float inv = 1.0f / (float)(cnt > 0 ? cnt : 1);
    acc.x *= inv; acc.y *= inv; acc.z *= inv; acc.w *= inv;
    *(float4*)(out + (size_t)w * Hc + lane * 4) = acc;
}

// ---------------- mma.sync bf16 helpers ----------------
__device__ __forceinline__ void ldm_x4(uint32_t& r0, uint32_t& r1, uint32_t& r2, uint32_t& r3, uint32_t addr) {
    asm volatile("ldmatrix.sync.aligned.m8n8.x4.shared.b16 {%0,%1,%2,%3}, [%4];"
                 : "=r"(r0), "=r"(r1), "=r"(r2), "=r"(r3) : "r"(addr));
}
__device__ __forceinline__ void ldm_x4_t(uint32_t& r0, uint32_t& r1, uint32_t& r2, uint32_t& r3, uint32_t addr) {
    asm volatile("ldmatrix.sync.aligned.m8n8.x4.trans.shared.b16 {%0,%1,%2,%3}, [%4];"
                 : "=r"(r0), "=r"(r1), "=r"(r2), "=r"(r3) : "r"(addr));
}
__device__ __forceinline__ void mma_bf16(float* c, const uint32_t* a, uint32_t b0, uint32_t b1) {
    asm volatile(
        "mma.sync.aligned.m16n8k16.row.col.f32.bf16.bf16.f32 "
        "{%0,%1,%2,%3}, {%4,%5,%6,%7}, {%8,%9}, {%0,%1,%2,%3};"
        : "+f"(c[0]), "+f"(c[1]), "+f"(c[2]), "+f"(c[3])
        : "r"(a[0]), "r"(a[1]), "r"(a[2]), "r"(a[3]), "r"(b0), "r"(b1));
}
__device__ __forceinline__ uint32_t pack_bf16(float x, float y) {
    uint32_t r;
    asm("cvt.rn.bf16x2.f32 %0, %1, %2;" : "=r"(r) : "f"(y), "f"(x));
    return r;
}

// ---------------- split-bf16 tensor-core GEMM (cp.async B path) ----------------
// C[M,128] = epi( A@W [+ A2@W2] + bias [+ flag*flagvec] )
static constexpr int SMA_STR_BUF = 10240;  // per A buf (2 parts)
static constexpr int SMA_STR_PART = 5120;
static constexpr int SMB_BASE = 20480;
static constexpr int SMB_STR_BUF = 17408;
static constexpr int SMB_STR_PART = 8704;
static constexpr int SM2_TOTAL = 55296;

template<bool RELU, bool DUAL, bool FLAGV>
__global__ void __launch_bounds__(256) gemm_mma2_kernel(
    const float* __restrict__ A,  const __nv_bfloat16* __restrict__ B,  int K,
    const float* __restrict__ A2, const __nv_bfloat16* __restrict__ B2,
    const float* __restrict__ bias,
    const float* __restrict__ flagvec, const int* __restrict__ flags,
    float* __restrict__ C, int M)
{
    extern __shared__ __align__(16) char smem[];

    const int tid = threadIdx.x;
    const int lane = tid & 31;
    const int wid = tid >> 5;
    const int wm = wid & 1;        // 0..1 : 32-row slice
    const int wn = wid >> 1;       // 0..3 : 32-col slice
    const int row0 = blockIdx.x * 64;

    const uint32_t sBase = (uint32_t)__cvta_generic_to_shared(&smem[0]);

    float acc[2][4][4];
    #pragma unroll
    for (int mi = 0; mi < 2; mi++)
        #pragma unroll
        for (int j = 0; j < 4; j++)
            #pragma unroll
            for (int q = 0; q < 4; q++) acc[mi][j][q] = 0.f;

    const int nk = K / 32;
    const int nchunks = (DUAL ? 2 : 1) * nk;

    float4 av[2];

    auto cp_b = [&](int c, int buf) {
        int s = (DUAL && c >= nk) ? 1 : 0;
        int kt = (s ? c - nk : c) * 32;
        const __nv_bfloat16* Bp = s ? B2 : B;
        #pragma unroll
        for (int p = 0; p < 2; p++)
            #pragma unroll
            for (int r = 0; r < 2; r++) {
                int idx = tid + r * 256;
                int kk = idx >> 4, h8 = idx & 15;
                uint32_t dst = sBase + SMB_BASE + buf * SMB_STR_BUF + p * SMB_STR_PART + kk * 272 + h8 * 16;
                const void* src = Bp + (size_t)p * K * 128 + (size_t)(kt + kk) * 128 + h8 * 8;
                asm volatile("cp.async.cg.shared.global [%0], [%1], 16;" :: "r"(dst), "l"(src));
            }
        asm volatile("cp.async.commit_group;" ::: "memory");
    };
    auto load_a = [&](int c) {
        int s = (DUAL && c >= nk) ? 1 : 0;
        int kt = (s ? c - nk : c) * 32;
        const float* Ap = s ? A2 : A;
        #pragma unroll
        for (int r = 0; r < 2; r++) {
            int idx = tid + r * 256;
            int m = idx >> 3, c4 = idx & 7;
            int row = row0 + m;
            av[r] = (row < M) ? *(const float4*)(Ap + (size_t)row * K + kt + c4 * 4)
                              : make_float4(0.f, 0.f, 0.f, 0.f);
        }
    };
    auto sts_a = [&](int buf) {
        #pragma unroll
        for (int r = 0; r < 2; r++) {
            int idx = tid + r * 256;
            int m = idx >> 3, c4 = idx & 7;
            float hx = bf_rn(av[r].x), hy = bf_rn(av[r].y);
            float hz = bf_rn(av[r].z), hw = bf_rn(av[r].w);
            uint2 hi, lo;
            hi.x = pack_bf16(hx, hy);
            hi.y = pack_bf16(hz, hw);
            lo.x = pack_bf16(av[r].x - hx, av[r].y - hy);
            lo.y = pack_bf16(av[r].z - hz, av[r].w - hw);
            int off = buf * SMA_STR_BUF + m * 80 + c4 * 8;
            *(uint2*)(&smem[off]) = hi;
            *(uint2*)(&smem[off + SMA_STR_PART]) = lo;
        }
    };

    cp_b(0, 0);
    load_a(0);
    sts_a(0);
    asm volatile("cp.async.wait_group 0;" ::: "memory");
    __syncthreads();

    for (int c = 0; c < nchunks; c++) {
        int buf = c & 1;
        if (c + 1 < nchunks) {
            cp_b(c + 1, buf ^ 1);
            load_a(c + 1);
        }

        uint32_t aHi = sBase + buf * SMA_STR_BUF;
        uint32_t aLo = aHi + SMA_STR_PART;
        uint32_t bHi = sBase + SMB_BASE + buf * SMB_STR_BUF;
        uint32_t bLo = bHi + SMB_STR_PART;

        #pragma unroll
        for (int ks = 0; ks < 2; ks++) {
            uint32_t aoff = (uint32_t)((wm * 32 + (lane & 15)) * 80 + ks * 32 + (lane >> 4) * 16);
            uint32_t ah[2][4], al[2][4];
            #pragma unroll
            for (int mi = 0; mi < 2; mi++) {
                ldm_x4(ah[mi][0], ah[mi][1], ah[mi][2], ah[mi][3], aHi + aoff + mi * 16 * 80);
                ldm_x4(al[mi][0], al[mi][1], al[mi][2], al[mi][3], aLo + aoff + mi * 16 * 80);
            }
            uint32_t bh[4][2], bl[4][2];
            #pragma unroll
            for (int p = 0; p < 2; p++) {
                int krow = ks * 16 + ((lane >> 3) & 1) * 8 + (lane & 7);
                int ncol = wn * 32 + p * 16 + (lane >> 4) * 8;
                uint32_t boff = (uint32_t)(krow * 272 + ncol * 2);
                ldm_x4_t(bh[2 * p][0], bh[2 * p][1], bh[2 * p + 1][0], bh[2 * p + 1][1], bHi + boff);
                ldm_x4_t(bl[2 * p][0], bl[2 * p][1], bl[2 * p + 1][0], bl[2 * p + 1][1], bLo + boff);
            }
            #pragma unroll
            for (int mi = 0; mi < 2; mi++)
                #pragma unroll
                for (int j = 0; j < 4; j++)
                    mma_bf16(acc[mi][j], ah[mi], bh[j][0], bh[j][1]);
            #pragma unroll
            for (int mi = 0; mi < 2; mi++)
                #pragma unroll
                for (int j = 0; j < 4; j++)
                    mma_bf16(acc[mi][j], ah[mi], bl[j][0], bl[j][1]);
            #pragma unroll
            for (int mi = 0; mi < 2; mi++)
                #pragma unroll
                for (int j = 0; j < 4; j++)
                    mma_bf16(acc[mi][j], al[mi], bh[j][0], bh[j][1]);
        }

        if (c + 1 < nchunks) {
            sts_a(buf ^ 1);
            asm volatile("cp.async.wait_group 0;" ::: "memory");
            __syncthreads();
        }
    }

    #pragma unroll
    for (int mi = 0; mi < 2; mi++) {
        int rl = row0 + wm * 32 + mi * 16 + (lane >> 2);
        int rh = rl + 8;
        float fl_l = 0.f, fl_h = 0.f;
        if (FLAGV) {
            if (rl < M) fl_l = (flags[rl] > 0) ? 1.f : 0.f;
            if (rh < M) fl_h = (flags[rh] > 0) ? 1.f : 0.f;
        }
        #pragma unroll
        for (int j = 0; j < 4; j++) {
            int col = wn * 32 + j * 8 + (lane & 3) * 2;
            float b0 = __ldg(&bias[col]), b1 = __ldg(&bias[col + 1]);
            float f0 = 0.f, f1 = 0.f;
            if (FLAGV) { f0 = __ldg(&flagvec[col]); f1 = __ldg(&flagvec[col + 1]); }
            float v0 = acc[mi][j][0] + b0;
            float v1 = acc[mi][j][1] + b1;
            float v2 = acc[mi][j][2] + b0;
            float v3 = acc[mi][j][3] + b1;
            if (FLAGV) { v0 += fl_l * f0; v1 += fl_l * f1; v2 += fl_h * f0; v3 += fl_h * f1; }
            if (RELU) {
                v0 = fmaxf(v0, 0.f); v1 = fmaxf(v1, 0.f);
                v2 = fmaxf(v2, 0.f); v3 = fmaxf(v3, 0.f);
            }
            if (rl < M) *(float2*)(C + (size_t)rl * 128 + col) = make_float2(v0, v1);
            if (rh < M) *(float2*)(C + (size_t)rh * 128 + col) = make_float2(v2, v3);
        }
    }
}

// ---------------- fused gather-mean + GEMM (conv1 user side) ----------------
// C[M,128] = relu( mean_agg(X)[M rows] @ W + bvec ), K=128 fixed.
// SMEM: A chunk c at c*10240 (hi +0, lo +5120, 64 rows x 80B each)
//       B chunk c at 40960 + c*17408 (hi +0, lo +8704, 32 rows x 272B each)
static constexpr int SMF_B_BASE = 40960;
static constexpr int SMF_TOTAL = 110592;

__global__ void __launch_bounds__(256, 2) gemm_gather_kernel(
    const int* __restrict__ off, const int* __restrict__ adj,
    const float* __restrict__ X,
    const __nv_bfloat16* __restrict__ B,
    const float* __restrict__ bvec,
    float* __restrict__ C, int M)
{
    extern __shared__ __align__(16) char smem[];
    const int tid = threadIdx.x;
    const int lane = tid & 31;
    const int wid = tid >> 5;
    const int wm = wid & 1;
    const int wn = wid >> 1;
    const int row0 = blockIdx.x * 64;
    const uint32_t sBase = (uint32_t)__cvta_generic_to_shared(&smem[0]);

    // ---- async copy of full B (K=128, hi+lo) ----
    #pragma unroll
    for (int p = 0; p < 2; p++)
        #pragma unroll
        for (int r = 0; r < 8; r++) {
            int idx = tid + r * 256;          // 0..2047
            int kk = idx >> 4, h8 = idx & 15;
            int chunk = kk >> 5, krow = kk & 31;
            uint32_t dst = sBase + SMF_B_BASE + chunk * 17408 + p * 8704 + krow * 272 + h8 * 16;
            const void* src = B + (size_t)p * 128 * 128 + (size_t)kk * 128 + h8 * 8;
            asm volatile("cp.async.cg.shared.global [%0], [%1], 16;" :: "r"(dst), "l"(src));
        }
    asm volatile("cp.async.commit_group;" ::: "memory");

    // ---- gather-mean A rows directly into SMEM (bf16 hi/lo) ----
    {
        int chunk = lane >> 3, c4 = lane & 7;
        #pragma unroll
        for (int rr = 0; rr < 8; rr++) {
            int row_local = wid * 8 + rr;
            int grow = row0 + row_local;
            float4 acc = make_float4(0.f, 0.f, 0.f, 0.f);
            if (grow < M) {
                int s = off[grow], e = off[grow + 1];
                int i = s;
                for (; i + 1 < e; i += 2) {
                    int j0 = adj[i], j1 = adj[i + 1];
                    float4 v0 = *(const float4*)(X + (size_t)j0 * Hc + lane * 4);
                    float4 v1 = *(const float4*)(X + (size_t)j1 * Hc + lane * 4);
                    acc.x += v0.x + v1.x; acc.y += v0.y + v1.y;
                    acc.z += v0.z + v1.z; acc.w += v0.w + v1.w;
                }
                if (i < e) {
                    int j = adj[i];
                    float4 v = *(const float4*)(X + (size_t)j * Hc + lane * 4);
                    acc.x += v.x; acc.y += v.y; acc.z += v.z; acc.w += v.w;
                }
                int cnt = e - s;
                float inv = 1.0f / (float)(cnt > 0 ? cnt : 1);
                acc.x *= inv; acc.y *= inv; acc.z *= inv; acc.w *= inv;
            }
            float hx = bf_rn(acc.x), hy = bf_rn(acc.y);
            float hz = bf_rn(acc.z), hw = bf_rn(acc.w);
            uint2 hi, lo;
            hi.x = pack_bf16(hx, hy);
            hi.y = pack_bf16(hz, hw);
            lo.x = pack_bf16(acc.x - hx, acc.y - hy);
            lo.y = pack_bf16(acc.z - hz, acc.w - hw);
            int offb = chunk * 10240 + row_local * 80 + c4 * 8;
            *(uint2*)(&smem[offb]) = hi;
            *(uint2*)(&smem[offb + 5120]) = lo;
        }
    }
    asm volatile("cp.async.wait_group 0;" ::: "memory");
    __syncthreads();

    // ---- MMA over 4 K-chunks ----
    float acc[2][4][4];
    #pragma unroll
    for (int mi = 0; mi < 2; mi++)
        #pragma unroll
        for (int j = 0; j < 4; j++)
            #pragma unroll
            for (int q = 0; q < 4; q++) acc[mi][j][q] = 0.f;

    #pragma unroll
    for (int c = 0; c < 4; c++) {
        uint32_t aHi = sBase + c * 10240;
        uint32_t aLo = aHi + 5120;
        uint32_t bHi = sBase + SMF_B_BASE + c * 17408;
        uint32_t bLo = bHi + 8704;
        #pragma unroll
        for (int ks = 0; ks < 2; ks++) {
            uint32_t aoff = (uint32_t)((wm * 32 + (lane & 15)) * 80 + ks * 32 + (lane >> 4) * 16);
            uint32_t ah[2][4], al[2][4];
            #pragma unroll
            for (int mi = 0; mi < 2; mi++) {
                ldm_x4(ah[mi][0], ah[mi][1], ah[mi][2], ah[mi][3], aHi + aoff + mi * 16 * 80);
                ldm_x4(al[mi][0], al[mi][1], al[mi][2], al[mi][3], aLo + aoff + mi * 16 * 80);
            }
            uint32_t bh[4][2], bl[4][2];
            #pragma unroll
            for (int p = 0; p < 2; p++) {
                int krow = ks * 16 + ((lane >> 3) & 1) * 8 + (lane & 7);
                int ncol = wn * 32 + p * 16 + (lane >> 4) * 8;
                uint32_t boff = (uint32_t)(krow * 272 + ncol * 2);
                ldm_x4_t(bh[2 * p][0], bh[2 * p][1], bh[2 * p + 1][0], bh[2 * p + 1][1], bHi + boff);
                ldm_x4_t(bl[2 * p][0], bl[2 * p][1], bl[2 * p + 1][0], bl[2 * p + 1][1], bLo + boff);
            }
            #pragma unroll
            for (int mi = 0; mi < 2; mi++)
                #pragma unroll
                for (int j = 0; j < 4; j++)
                    mma_bf16(acc[mi][j], ah[mi], bh[j][0], bh[j][1]);
            #pragma unroll
            for (int mi = 0; mi < 2; mi++)
                #pragma unroll
                for (int j = 0; j < 4; j++)
                    mma_bf16(acc[mi][j], ah[mi], bl[j][0], bl[j][1]);
            #pragma unroll
            for (int mi = 0; mi < 2; mi++)
                #pragma unroll
                for (int j = 0; j < 4; j++)
                    mma_bf16(acc[mi][j], al[mi], bh[j][0], bh[j][1]);
        }
    }

    // ---- epilogue: bias (bvec) + relu ----
    #pragma unroll
    for (int mi = 0; mi < 2; mi++) {
        int rl = row0 + wm * 32 + mi * 16 + (lane >> 2);
        int rh = rl + 8;
        #pragma unroll
        for (int j = 0; j < 4; j++) {
            int col = wn * 32 + j * 8 + (lane & 3) * 2;
            float b0 = __ldg(&bvec[col]), b1 = __ldg(&bvec[col + 1]);
            float v0 = fmaxf(acc[mi][j][0] + b0, 0.f);
            float v1 = fmaxf(acc[mi][j][1] + b1, 0.f);
            float v2 = fmaxf(acc[mi][j][2] + b0, 0.f);
            float v3 = fmaxf(acc[mi][j][3] + b1, 0.f);
            if (rl < M) *(float2*)(C + (size_t)rl * 128 + col) = make_float2(v0, v1);
            if (rh < M) *(float2*)(C + (size_t)rh * 128 + col) = make_float2(v2, v3);
        }
    }
}

// ---------------- final edge-wise dot: one warp per supervision edge ----------------
__global__ void dot_kernel(const int* __restrict__ lu, const int* __restrict__ lm,
                           const float* __restrict__ U, const float* __restrict__ Mo,
                           float* __restrict__ out, int n) {
    int w = (blockIdx.x * blockDim.x + threadIdx.x) >> 5;
    int lane = threadIdx.x & 31;
    if (w >= n) return;
    int u = lu[w], m = lm[w];
    float4 a = *(const float4*)(U  + (size_t)u * Hc + lane * 4);
    float4 b = *(const float4*)(Mo + (size_t)m * Hc + lane * 4);
    float p = a.x * b.x + a.y * b.y + a.z * b.z + a.w * b.w;
    #pragma unroll
    for (int o = 16; o > 0; o >>= 1) p += __shfl_xor_sync(0xFFFFFFFFu, p, o);
    if (lane == 0) out[w] = p;
}

// ---------------- host launcher ----------------
extern "C" void kernel_launch(void* const* d_in, const int* in_sizes, int n_in,
                              void* d_out, int out_size) {
    const float* movie_feats = (const float*)d_in[0];
    const float* user_init   = (const float*)d_in[1];
    const int*   edge_src    = (const int*)d_in[2];
    const int*   edge_dst    = (const int*)d_in[3];
    const int*   lbl_user    = (const int*)d_in[4];
    const int*   lbl_movie   = (const int*)d_in[5];
    int wb = (in_sizes[6] == FDc * Hc) ? 6 : 7;
    const float* Wm     = (const float*)d_in[wb + 0];
    const float* bm     = (const float*)d_in[wb + 1];
    const float* Wl1_um = (const float*)d_in[wb + 2];
    const float* bl1_um = (const float*)d_in[wb + 3];
    const float* Wr1_um = (const float*)d_in[wb + 4];
    const float* Wl1_mu = (const float*)d_in[wb + 5];
    const float* bl1_mu = (const float*)d_in[wb + 6];
    const float* Wr1_mu = (const float*)d_in[wb + 7];
    const float* Wl2_um = (const float*)d_in[wb + 8];
    const float* bl2_um = (const float*)d_in[wb + 9];
    const float* Wr2_um = (const float*)d_in[wb + 10];
    const float* Wl2_mu = (const float*)d_in[wb + 11];
    const float* bl2_mu = (const float*)d_in[wb + 12];
    const float* Wr2_mu = (const float*)d_in[wb + 13];

    float* out = (float*)d_out;

    void *p_movie_x, *p_movie_h, *p_aggM, *p_user_h, *p_user_o, *p_aggU2;
    void *p_cnt_m, *p_cnt_u, *p_off_m, *p_off_u, *p_pos_m, *p_pos_u;
    void *p_adj_m, *p_adj_u, *p_bsum_m, *p_bsum_u, *p_cvec, *p_bvec, *p_wpool;
    cudaGetSymbolAddress(&p_movie_x, g_movie_x);
    cudaGetSymbolAddress(&p_movie_h, g_movie_h);
    cudaGetSymbolAddress(&p_aggM,   g_aggM);
    cudaGetSymbolAddress(&p_user_h, g_user_h);
    cudaGetSymbolAddress(&p_user_o, g_user_o);
    cudaGetSymbolAddress(&p_aggU2,  g_aggU2);
    cudaGetSymbolAddress(&p_cnt_m,  g_cnt_m);
    cudaGetSymbolAddress(&p_cnt_u,  g_cnt_u);
    cudaGetSymbolAddress(&p_off_m,  g_off_m);
    cudaGetSymbolAddress(&p_off_u,  g_off_u);
    cudaGetSymbolAddress(&p_pos_m,  g_pos_m);
    cudaGetSymbolAddress(&p_pos_u,  g_pos_u);
    cudaGetSymbolAddress(&p_adj_m,  g_adj_m);
    cudaGetSymbolAddress(&p_adj_u,  g_adj_u);
    cudaGetSymbolAddress(&p_bsum_m, g_bsum_m);
    cudaGetSymbolAddress(&p_bsum_u, g_bsum_u);
    cudaGetSymbolAddress(&p_cvec,   g_cvec);
    cudaGetSymbolAddress(&p_bvec,   g_bvec_u1);
    cudaGetSymbolAddress(&p_wpool,  g_wpool);

    float* movie_x = (float*)p_movie_x;
    float* movie_h = (float*)p_movie_h;
    float* aggM    = (float*)p_aggM;
    float* user_h  = (float*)p_user_h;
    float* user_o  = (float*)p_user_o;
    float* aggU2   = (float*)p_aggU2;
    int* cnt_m = (int*)p_cnt_m; int* cnt_u = (int*)p_cnt_u;
    int* off_m = (int*)p_off_m; int* off_u = (int*)p_off_u;
    int* pos_m = (int*)p_pos_m; int* pos_u = (int*)p_pos_u;
    int* adj_m = (int*)p_adj_m; int* adj_u = (int*)p_adj_u;
    int* bsum_m = (int*)p_bsum_m; int* bsum_u = (int*)p_bsum_u;
    float* cvec = (float*)p_cvec; float* bvec_u1 = (float*)p_bvec;
    __nv_bfloat16* wpool = (__nv_bfloat16*)p_wpool;

    cudaFuncSetAttribute(gemm_mma2_kernel<false, false, false>, cudaFuncAttributeMaxDynamicSharedMemorySize, SM2_TOTAL);
    cudaFuncSetAttribute(gemm_mma2_kernel<true,  false, true >, cudaFuncAttributeMaxDynamicSharedMemorySize, SM2_TOTAL);
    cudaFuncSetAttribute(gemm_mma2_kernel<false, true,  false>, cudaFuncAttributeMaxDynamicSharedMemorySize, SM2_TOTAL);
    cudaFuncSetAttribute(gemm_gather_kernel, cudaFuncAttributeMaxDynamicSharedMemorySize, SMF_TOTAL);

    const int nbM = (NMc + 1023) / 1024;
    const int nbU = (NUc + 1023) / 1024;
    const int gM = (NMc + 63) / 64;     // 1250
    const int gU = (NUc + 63) / 64;     // 3125

    cudaStream_t s1 = g_sr.s1;

    // ======== fork ========
    cudaEventRecord(g_sr.eFork, 0);
    cudaStreamWaitEvent(s1, g_sr.eFork, 0);

    // ---- s0: wconv(Wm) -> GEMM1 immediately (shortest critical prefix) ----
    wconv_kernel<<<(FDc * Hc + 255) / 256, 256>>>(Wm, wpool + OFF_WM, FDc * Hc);
    gemm_mma2_kernel<false, false, false><<<gM, 256, SM2_TOTAL>>>(
        movie_feats, wpool + OFF_WM, FDc, nullptr, nullptr, bm, nullptr, nullptr, movie_x, NMc);
    cudaEventRecord(g_sr.eG1, 0);

    // ---- s1: small wconvs + prevec, then CSR build ----
    wconv_kernel<<<(Hc * Hc + 255) / 256, 256, 0, s1>>>(Wl1_mu, wpool + OFF_WL1MU, Hc * Hc);
    wconv_kernel<<<(Hc * Hc + 255) / 256, 256, 0, s1>>>(Wr1_um, wpool + OFF_WR1UM, Hc * Hc);
    wconv_kernel<<<(Hc * Hc + 255) / 256, 256, 0, s1>>>(Wl2_um, wpool + OFF_WL2UM, Hc * Hc);
    wconv_kernel<<<(Hc * Hc + 255) / 256, 256, 0, s1>>>(Wr2_um, wpool + OFF_WR2UM, Hc * Hc);
    wconv_kernel<<<(Hc * Hc + 255) / 256, 256, 0, s1>>>(Wl2_mu, wpool + OFF_WL2MU, Hc * Hc);
    wconv_kernel<<<(Hc * Hc + 255) / 256, 256, 0, s1>>>(Wr2_mu, wpool + OFF_WR2MU, Hc * Hc);
    prevec_kernel<<<1, Hc, 0, s1>>>(user_init, Wl1_um, Wr1_mu, bl1_mu, cvec, bvec_u1);

    zero_int_kernel<<<(NMc + 255) / 256, 256, 0, s1>>>(cnt_m, NMc);
    zero_int_kernel<<<(NUc + 255) / 256, 256, 0, s1>>>(cnt_u, NUc);
    hist_kernel<<<2048, 256, 0, s1>>>(edge_src, edge_dst, cnt_u, cnt_m, Ec);
    cudaEventRecord(g_sr.eHist, s1);
    scan_block_kernel<<<nbM, 1024, 0, s1>>>(cnt_m, off_m, bsum_m, NMc);
    scan_sums_kernel<<<1, 32, 0, s1>>>(bsum_m, nbM);
    scan_add_kernel<<<nbM, 1024, 0, s1>>>(off_m, bsum_m, NMc);
    scan_block_kernel<<<nbU, 1024, 0, s1>>>(cnt_u, off_u, bsum_u, NUc);
    scan_sums_kernel<<<1, 32, 0, s1>>>(bsum_u, nbU);
    scan_add_kernel<<<nbU, 1024, 0, s1>>>(off_u, bsum_u, NUc);
    copy_int_kernel<<<(NMc + 255) / 256, 256, 0, s1>>>(pos_m, off_m, NMc);
    copy_int_kernel<<<(NUc + 255) / 256, 256, 0, s1>>>(pos_u, off_u, NUc);
    place_kernel<<<2048, 256, 0, s1>>>(edge_src, edge_dst, pos_u, pos_m, adj_u, adj_m, Ec);
    cudaEventRecord(g_sr.eCsr, s1);

    // ---- s0 chain B: movie_h -> aggU2 -> user_o ----
    cudaStreamWaitEvent(0, g_sr.eHist, 0);   // cnt_m + wconv(Wr1_um) + prevec ready
    gemm_mma2_kernel<true, false, true><<<gM, 256, SM2_TOTAL>>>(
        movie_x, wpool + OFF_WR1UM, Hc, nullptr, nullptr, bl1_um, cvec, cnt_m, movie_h, NMc);
    cudaEventRecord(g_sr.eMH, 0);

    // ---- s1 chain A: fused user_h -> aggM -> movie_o ----
    cudaStreamWaitEvent(s1, g_sr.eG1, 0);    // movie_x ready (CSR in-stream)
    gemm_gather_kernel<<<gU, 256, SMF_TOTAL, s1>>>(
        off_u, adj_u, movie_x, wpool + OFF_WL1MU, bvec_u1, user_h, NUc);
    cudaEventRecord(g_sr.eUH, s1);
    agg_mean_kernel<<<(NMc * 32 + 255) / 256, 256, 0, s1>>>(off_m, adj_m, user_h, aggM, NMc);
    cudaStreamWaitEvent(s1, g_sr.eMH, 0);
    gemm_mma2_kernel<false, true, false><<<gM, 256, SM2_TOTAL, s1>>>(
        aggM, wpool + OFF_WL2UM, Hc, movie_h, wpool + OFF_WR2UM, bl2_um, nullptr, nullptr, movie_x, NMc);
    cudaEventRecord(g_sr.eMO, s1);

    // ---- s0: aggU2 (needs movie_h in-stream + CSR) -> user_o ----
    cudaStreamWaitEvent(0, g_sr.eCsr, 0);
    agg_mean_kernel<<<(NUc * 32 + 255) / 256, 256>>>(off_u, adj_u, movie_h, aggU2, NUc);
    cudaStreamWaitEvent(0, g_sr.eUH, 0);
    gemm_mma2_kernel<false, true, false><<<gU, 256, SM2_TOTAL>>>(
        aggU2, wpool + OFF_WL2MU, Hc, user_h, wpool + OFF_WR2MU, bl2_mu, nullptr, nullptr, user_o, NUc);

    // ---- join + dot ----
    cudaStreamWaitEvent(0, g_sr.eMO, 0);
    dot_kernel<<<(ELc * 32 + 255) / 256, 256>>>(lbl_user, lbl_movie, user_o, movie_x, out, ELc);
}

// round 11
// speedup vs baseline: 1.0122x; 1.0122x over previous
#include <cuda_runtime.h>
#include <cuda_bf16.h>
#include <cstdint>

// Problem-size constants (fixed by the dataset)
#define NUc 200000
#define NMc 80000
#define Ec  2000000
#define ELc 500000
#define Hc  128
#define FDc 512

// ---------------- scratch (static device allocations; no cudaMalloc) ----------------
__device__ float g_movie_x[NMc * Hc];   // movie_x; later reused as movie_o
__device__ float g_movie_h[NMc * Hc];
__device__ float g_aggM  [NMc * Hc];
__device__ float g_user_h[NUc * Hc];
__device__ float g_user_o[NUc * Hc];
__device__ float g_aggU  [NUc * Hc];    // conv1 user aggregation
__device__ float g_aggU2 [NUc * Hc];    // conv2 user aggregation

__device__ int g_cnt_m[NMc];
__device__ int g_cnt_u[NUc];
__device__ int g_off_m[NMc + 1];
__device__ int g_off_u[NUc + 1];
__device__ int g_pos_m[NMc];
__device__ int g_pos_u[NUc];
__device__ int g_adj_m[Ec];             // user ids grouped by movie
__device__ int g_adj_u[Ec];             // movie ids grouped by user
__device__ int g_bsum_m[256];
__device__ int g_bsum_u[256];
__device__ float g_cvec[Hc];            // u0 @ Wl1_um
__device__ float g_bvec_u1[Hc];         // bl1_mu + u0 @ Wr1_mu

// bf16 hi/lo weight pool: [hi K*128][lo K*128] per matrix
#define OFF_WM     0
#define OFF_WL1MU  131072
#define OFF_WR1UM  163840
#define OFF_WL2UM  196608
#define OFF_WR2UM  229376
#define OFF_WL2MU  262144
#define OFF_WR2MU  294912
__device__ __nv_bfloat16 g_wpool[327680];

// ---------------- host-side stream/event resources (created pre-main) ----------------
struct StreamRes {
    cudaStream_t s1;
    cudaEvent_t eFork, eHist, eCsr, eG1, eMH, eUH, eMO1, eMO;
    StreamRes() {
        cudaStreamCreateWithFlags(&s1, cudaStreamNonBlocking);
        cudaEventCreateWithFlags(&eFork, cudaEventDisableTiming);
        cudaEventCreateWithFlags(&eHist, cudaEventDisableTiming);
        cudaEventCreateWithFlags(&eCsr,  cudaEventDisableTiming);
        cudaEventCreateWithFlags(&eG1,   cudaEventDisableTiming);
        cudaEventCreateWithFlags(&eMH,   cudaEventDisableTiming);
        cudaEventCreateWithFlags(&eUH,   cudaEventDisableTiming);
        cudaEventCreateWithFlags(&eMO1,  cudaEventDisableTiming);
        cudaEventCreateWithFlags(&eMO,   cudaEventDisableTiming);
    }
};
static StreamRes g_sr;

// ---------------- small utility kernels ----------------
__global__ void zero_int_kernel(int* p, int n) {
    int i = blockIdx.x * blockDim.x + threadIdx.x;
    if (i < n) p[i] = 0;
}
__global__ void copy_int_kernel(int* dst, const int* src, int n) {
    int i = blockIdx.x * blockDim.x + threadIdx.x;
    if (i < n) dst[i] = src[i];
}
__global__ void hist_kernel(const int* __restrict__ src, const int* __restrict__ dst,
                            int* cnt_u, int* cnt_m, int n) {
    for (int e = blockIdx.x * blockDim.x + threadIdx.x; e < n; e += gridDim.x * blockDim.x) {
        atomicAdd(&cnt_m[dst[e]], 1);
        atomicAdd(&cnt_u[src[e]], 1);
    }
}
__global__ void place_kernel(const int* __restrict__ src, const int* __restrict__ dst,
                             int* pos_u, int* pos_m, int* adj_u, int* adj_m, int n) {
    for (int e = blockIdx.x * blockDim.x + threadIdx.x; e < n; e += gridDim.x * blockDim.x) {
        int s = src[e], d = dst[e];
        int p = atomicAdd(&pos_m[d], 1);
        adj_m[p] = s;
        int q = atomicAdd(&pos_u[s], 1);
        adj_u[q] = d;
    }
}
__global__ void scan_block_kernel(const int* __restrict__ cnt, int* out, int* bsums, int n) {
    __shared__ int sh[1024];
    int tid = threadIdx.x;
    int i = blockIdx.x * 1024 + tid;
    int v = (i < n) ? cnt[i] : 0;
    sh[tid] = v;
    __syncthreads();
    #pragma unroll
    for (int off = 1; off < 1024; off <<= 1) {
        int t = (tid >= off) ? sh[tid - off] : 0;
        __syncthreads();
        sh[tid] += t;
        __syncthreads();
    }
    if (i < n) out[i + 1] = sh[tid];
    if (tid == 1023) bsums[blockIdx.x] = sh[1023];
}
__global__ void scan_sums_kernel(int* bsums, int nb) {
    if (threadIdx.x == 0 && blockIdx.x == 0) {
        int acc = 0;
        for (int b = 0; b < nb; b++) { int v = bsums[b]; bsums[b] = acc; acc += v; }
    }
}
__global__ void scan_add_kernel(int* out, const int* __restrict__ bsums, int n) {
    int i = blockIdx.x * 1024 + threadIdx.x;
    if (i < n) out[i + 1] += bsums[blockIdx.x];
    if (i == 0) out[0] = 0;
}
__global__ void prevec_kernel(const float* __restrict__ u0,
                              const float* __restrict__ Wl1um,
                              const float* __restrict__ Wr1mu,
                              const float* __restrict__ bl1mu,
                              float* cvec, float* bvec) {
    int j = threadIdx.x;
    float c = 0.f, r = 0.f;
    for (int k = 0; k < Hc; k++) {
        float u = u0[k];
        c += u * Wl1um[k * Hc + j];
        r += u * Wr1mu[k * Hc + j];
    }
    cvec[j] = c;
    bvec[j] = bl1mu[j] + r;
}

__device__ __forceinline__ float bf_rn(float v) {
    return __bfloat162float(__float2bfloat16_rn(v));
}
// weight pre-conversion: out[0..n) = hi(bf16), out[n..2n) = lo(bf16)
__global__ void wconv_kernel(const float* __restrict__ W, __nv_bfloat16* out, int n) {
    int i = blockIdx.x * blockDim.x + threadIdx.x;
    if (i < n) {
        float w = W[i];
        float h = bf_rn(w);
        out[i] = __float2bfloat16_rn(h);
        out[n + i] = __float2bfloat16_rn(w - h);
    }
}

// ---------------- scatter-mean via CSR gather: one warp per destination node ----------------
__global__ void agg_mean_kernel(const int* __restrict__ off, const int* __restrict__ adj,
                                const float* __restrict__ X, float* __restrict__ out, int n) {
    int w = (blockIdx.x * blockDim.x + threadIdx.x) >> 5;
    int lane = threadIdx.x & 31;
    if (w >= n) return;
    int s = off[w], e = off[w + 1];
    float4 acc = make_float4(0.f, 0.f, 0.f, 0.f);
    int i = s;
    for (; i + 1 < e; i += 2) {
        int j0 = adj[i], j1 = adj[i + 1];
        float4 v0 = *(const float4*)(X + (size_t)j0 * Hc + lane * 4);
        float4 v1 = *(const float4*)(X + (size_t)j1 * Hc + lane * 4);
        acc.x += v0.x + v1.x; acc.y += v0.y + v1.y;
        acc.z += v0.z + v1.z; acc.w += v0.w + v1.w;
    }
    if (i < e) {
        int j = adj[i];
        float4 v = *(const float4*)(X + (size_t)j * Hc + lane * 4);
        acc.x += v.x; acc.y += v.y; acc.z += v.z; acc.w += v.w;
    }
    int cnt = e - s;
    float inv = 1.0f / (float)(cnt > 0 ? cnt : 1);
    acc.x *= inv; acc.y *= inv; acc.z *= inv; acc.w *= inv;
    *(float4*)(out + (size_t)w * Hc + lane * 4) = acc;
}

// ---------------- mma.sync bf16 helpers ----------------
__device__ __forceinline__ void ldm_x4(uint32_t& r0, uint32_t& r1, uint32_t& r2, uint32_t& r3, uint32_t addr) {
    asm volatile("ldmatrix.sync.aligned.m8n8.x4.shared.b16 {%0,%1,%2,%3}, [%4];"
                 : "=r"(r0), "=r"(r1), "=r"(r2), "=r"(r3) : "r"(addr));
}
__device__ __forceinline__ void ldm_x4_t(uint32_t& r0, uint32_t& r1, uint32_t& r2, uint32_t& r3, uint32_t addr) {
    asm volatile("ldmatrix.sync.aligned.m8n8.x4.trans.shared.b16 {%0,%1,%2,%3}, [%4];"
                 : "=r"(r0), "=r"(r1), "=r"(r2), "=r"(r3) : "r"(addr));
}
__device__ __forceinline__ void mma_bf16(float* c, const uint32_t* a, uint32_t b0, uint32_t b1) {
    asm volatile(
        "mma.sync.aligned.m16n8k16.row.col.f32.bf16.bf16.f32 "
        "{%0,%1,%2,%3}, {%4,%5,%6,%7}, {%8,%9}, {%0,%1,%2,%3};"
        : "+f"(c[0]), "+f"(c[1]), "+f"(c[2]), "+f"(c[3])
        : "r"(a[0]), "r"(a[1]), "r"(a[2]), "r"(a[3]), "r"(b0), "r"(b1));
}
__device__ __forceinline__ uint32_t pack_bf16(float x, float y) {
    uint32_t r;
    asm("cvt.rn.bf16x2.f32 %0, %1, %2;" : "=r"(r) : "f"(y), "f"(x));
    return r;
}

// ---------------- split-bf16 tensor-core GEMM (cp.async B path) ----------------
// Pass semantics:
//   ACC=false: C = epi( A@W + bias [+ flag*flagvec] )
//   ACC=true : C = C + A@W          (bias handled by the earlier pass)
static constexpr int SMA_STR_BUF = 10240;  // per A buf (2 parts)
static constexpr int SMA_STR_PART = 5120;
static constexpr int SMB_BASE = 20480;
static constexpr int SMB_STR_BUF = 17408;
static constexpr int SMB_STR_PART = 8704;
static constexpr int SM2_TOTAL = 55296;

template<bool RELU, bool ACC, bool FLAGV>
__global__ void __launch_bounds__(256) gemm_mma2_kernel(
    const float* __restrict__ A,  const __nv_bfloat16* __restrict__ B,  int K,
    const float* __restrict__ bias,
    const float* __restrict__ flagvec, const int* __restrict__ flags,
    float* __restrict__ C, int M)
{
    extern __shared__ __align__(16) char smem[];

    const int tid = threadIdx.x;
    const int lane = tid & 31;
    const int wid = tid >> 5;
    const int wm = wid & 1;        // 0..1 : 32-row slice
    const int wn = wid >> 1;       // 0..3 : 32-col slice
    const int row0 = blockIdx.x * 64;

    const uint32_t sBase = (uint32_t)__cvta_generic_to_shared(&smem[0]);

    float acc[2][4][4];
    #pragma unroll
    for (int mi = 0; mi < 2; mi++)
        #pragma unroll
        for (int j = 0; j < 4; j++)
            #pragma unroll
            for (int q = 0; q < 4; q++) acc[mi][j][q] = 0.f;

    const int nchunks = K / 32;

    float4 av[2];

    auto cp_b = [&](int c, int buf) {
        int kt = c * 32;
        #pragma unroll
        for (int p = 0; p < 2; p++)
            #pragma unroll
            for (int r = 0; r < 2; r++) {
                int idx = tid + r * 256;
                int kk = idx >> 4, h8 = idx & 15;
                uint32_t dst = sBase + SMB_BASE + buf * SMB_STR_BUF + p * SMB_STR_PART + kk * 272 + h8 * 16;
                const void* src = B + (size_t)p * K * 128 + (size_t)(kt + kk) * 128 + h8 * 8;
                asm volatile("cp.async.cg.shared.global [%0], [%1], 16;" :: "r"(dst), "l"(src));
            }
        asm volatile("cp.async.commit_group;" ::: "memory");
    };
    auto load_a = [&](int c) {
        int kt = c * 32;
        #pragma unroll
        for (int r = 0; r < 2; r++) {
            int idx = tid + r * 256;
            int m = idx >> 3, c4 = idx & 7;
            int row = row0 + m;
            av[r] = (row < M) ? *(const float4*)(A + (size_t)row * K + kt + c4 * 4)
                              : make_float4(0.f, 0.f, 0.f, 0.f);
        }
    };
    auto sts_a = [&](int buf) {
        #pragma unroll
        for (int r = 0; r < 2; r++) {
            int idx = tid + r * 256;
            int m = idx >> 3, c4 = idx & 7;
            float hx = bf_rn(av[r].x), hy = bf_rn(av[r].y);
            float hz = bf_rn(av[r].z), hw = bf_rn(av[r].w);
            uint2 hi, lo;
            hi.x = pack_bf16(hx, hy);
            hi.y = pack_bf16(hz, hw);
            lo.x = pack_bf16(av[r].x - hx, av[r].y - hy);
            lo.y = pack_bf16(av[r].z - hz, av[r].w - hw);
            int off = buf * SMA_STR_BUF + m * 80 + c4 * 8;
            *(uint2*)(&smem[off]) = hi;
            *(uint2*)(&smem[off + SMA_STR_PART]) = lo;
        }
    };

    cp_b(0, 0);
    load_a(0);
    sts_a(0);
    asm volatile("cp.async.wait_group 0;" ::: "memory");
    __syncthreads();

    for (int c = 0; c < nchunks; c++) {
        int buf = c & 1;
        if (c + 1 < nchunks) {
            cp_b(c + 1, buf ^ 1);
            load_a(c + 1);
        }

        uint32_t aHi = sBase + buf * SMA_STR_BUF;
        uint32_t aLo = aHi + SMA_STR_PART;
        uint32_t bHi = sBase + SMB_BASE + buf * SMB_STR_BUF;
        uint32_t bLo = bHi + SMB_STR_PART;

        #pragma unroll
        for (int ks = 0; ks < 2; ks++) {
            uint32_t aoff = (uint32_t)((wm * 32 + (lane & 15)) * 80 + ks * 32 + (lane >> 4) * 16);
            uint32_t ah[2][4], al[2][4];
            #pragma unroll
            for (int mi = 0; mi < 2; mi++) {
                ldm_x4(ah[mi][0], ah[mi][1], ah[mi][2], ah[mi][3], aHi + aoff + mi * 16 * 80);
                ldm_x4(al[mi][0], al[mi][1], al[mi][2], al[mi][3], aLo + aoff + mi * 16 * 80);
            }
            uint32_t bh[4][2], bl[4][2];
            #pragma unroll
            for (int p = 0; p < 2; p++) {
                int krow = ks * 16 + ((lane >> 3) & 1) * 8 + (lane & 7);
                int ncol = wn * 32 + p * 16 + (lane >> 4) * 8;
                uint32_t boff = (uint32_t)(krow * 272 + ncol * 2);
                ldm_x4_t(bh[2 * p][0], bh[2 * p][1], bh[2 * p + 1][0], bh[2 * p + 1][1], bHi + boff);
                ldm_x4_t(bl[2 * p][0], bl[2 * p][1], bl[2 * p + 1][0], bl[2 * p + 1][1], bLo + boff);
            }
            #pragma unroll
            for (int mi = 0; mi < 2; mi++)
                #pragma unroll
                for (int j = 0; j < 4; j++)
                    mma_bf16(acc[mi][j], ah[mi], bh[j][0], bh[j][1]);
            #pragma unroll
            for (int mi = 0; mi < 2; mi++)
                #pragma unroll
                for (int j = 0; j < 4; j++)
                    mma_bf16(acc[mi][j], ah[mi], bl[j][0], bl[j][1]);
            #pragma unroll
            for (int mi = 0; mi < 2; mi++)
                #pragma unroll
                for (int j = 0; j < 4; j++)
                    mma_bf16(acc[mi][j], al[mi], bh[j][0], bh[j][1]);
        }

        if (c + 1 < nchunks) {
            sts_a(buf ^ 1);
            asm volatile("cp.async.wait_group 0;" ::: "memory");
            __syncthreads();
        }
    }

    // ---- epilogue ----
    #pragma unroll
    for (int mi = 0; mi < 2; mi++) {
        int rl = row0 + wm * 32 + mi * 16 + (lane >> 2);
        int rh = rl + 8;
        float fl_l = 0.f, fl_h = 0.f;
        if (FLAGV) {
            if (rl < M) fl_l = (flags[rl] > 0) ? 1.f : 0.f;
            if (rh < M) fl_h = (flags[rh] > 0) ? 1.f : 0.f;
        }
        #pragma unroll
        for (int j = 0; j < 4; j++) {
            int col = wn * 32 + j * 8 + (lane & 3) * 2;
            float v0 = acc[mi][j][0];
            float v1 = acc[mi][j][1];
            float v2 = acc[mi][j][2];
            float v3 = acc[mi][j][3];
            if (ACC) {
                if (rl < M) {
                    float2 c0 = *(const float2*)(C + (size_t)rl * 128 + col);
                    v0 += c0.x; v1 += c0.y;
                }
                if (rh < M) {
                    float2 c1 = *(const float2*)(C + (size_t)rh * 128 + col);
                    v2 += c1.x; v3 += c1.y;
                }
            } else {
                float b0 = __ldg(&bias[col]), b1 = __ldg(&bias[col + 1]);
                v0 += b0; v1 += b1; v2 += b0; v3 += b1;
                if (FLAGV) {
                    float f0 = __ldg(&flagvec[col]), f1 = __ldg(&flagvec[col + 1]);
                    v0 += fl_l * f0; v1 += fl_l * f1; v2 += fl_h * f0; v3 += fl_h * f1;
                }
            }
            if (RELU) {
                v0 = fmaxf(v0, 0.f); v1 = fmaxf(v1, 0.f);
                v2 = fmaxf(v2, 0.f); v3 = fmaxf(v3, 0.f);
            }
            if (rl < M) *(float2*)(C + (size_t)rl * 128 + col) = make_float2(v0, v1);
            if (rh < M) *(float2*)(C + (size_t)rh * 128 + col) = make_float2(v2, v3);
        }
    }
}

// ---------------- final edge-wise dot: one warp per supervision edge ----------------
__global__ void dot_kernel(const int* __restrict__ lu, const int* __restrict__ lm,
                           const float* __restrict__ U, const float* __restrict__ Mo,
                           float* __restrict__ out, int n) {
    int w = (blockIdx.x * blockDim.x + threadIdx.x) >> 5;
    int lane = threadIdx.x & 31;
    if (w >= n) return;
    int u = lu[w], m = lm[w];
    float4 a = *(const float4*)(U  + (size_t)u * Hc + lane * 4);
    float4 b = *(const float4*)(Mo + (size_t)m * Hc + lane * 4);
    float p = a.x * b.x + a.y * b.y + a.z * b.z + a.w * b.w;
    #pragma unroll
    for (int o = 16; o > 0; o >>= 1) p += __shfl_xor_sync(0xFFFFFFFFu, p, o);
    if (lane == 0) out[w] = p;
}

// ---------------- host launcher ----------------
extern "C" void kernel_launch(void* const* d_in, const int* in_sizes, int n_in,
                              void* d_out, int out_size) {
    const float* movie_feats = (const float*)d_in[0];
    const float* user_init   = (const float*)d_in[1];
    const int*   edge_src    = (const int*)d_in[2];
    const int*   edge_dst    = (const int*)d_in[3];
    const int*   lbl_user    = (const int*)d_in[4];
    const int*   lbl_movie   = (const int*)d_in[5];
    int wb = (in_sizes[6] == FDc * Hc) ? 6 : 7;
    const float* Wm     = (const float*)d_in[wb + 0];
    const float* bm     = (const float*)d_in[wb + 1];
    const float* Wl1_um = (const float*)d_in[wb + 2];
    const float* bl1_um = (const float*)d_in[wb + 3];
    const float* Wr1_um = (const float*)d_in[wb + 4];
    const float* Wl1_mu = (const float*)d_in[wb + 5];
    const float* bl1_mu = (const float*)d_in[wb + 6];
    const float* Wr1_mu = (const float*)d_in[wb + 7];
    const float* Wl2_um = (const float*)d_in[wb + 8];
    const float* bl2_um = (const float*)d_in[wb + 9];
    const float* Wr2_um = (const float*)d_in[wb + 10];
    const float* Wl2_mu = (const float*)d_in[wb + 11];
    const float* bl2_mu = (const float*)d_in[wb + 12];
    const float* Wr2_mu = (const float*)d_in[wb + 13];

    float* out = (float*)d_out;

    void *p_movie_x, *p_movie_h, *p_aggM, *p_user_h, *p_user_o, *p_aggU, *p_aggU2;
    void *p_cnt_m, *p_cnt_u, *p_off_m, *p_off_u, *p_pos_m, *p_pos_u;
    void *p_adj_m, *p_adj_u, *p_bsum_m, *p_bsum_u, *p_cvec, *p_bvec, *p_wpool;
    cudaGetSymbolAddress(&p_movie_x, g_movie_x);
    cudaGetSymbolAddress(&p_movie_h, g_movie_h);
    cudaGetSymbolAddress(&p_aggM,   g_aggM);
    cudaGetSymbolAddress(&p_user_h, g_user_h);
    cudaGetSymbolAddress(&p_user_o, g_user_o);
    cudaGetSymbolAddress(&p_aggU,   g_aggU);
    cudaGetSymbolAddress(&p_aggU2,  g_aggU2);
    cudaGetSymbolAddress(&p_cnt_m,  g_cnt_m);
    cudaGetSymbolAddress(&p_cnt_u,  g_cnt_u);
    cudaGetSymbolAddress(&p_off_m,  g_off_m);
    cudaGetSymbolAddress(&p_off_u,  g_off_u);
    cudaGetSymbolAddress(&p_pos_m,  g_pos_m);
    cudaGetSymbolAddress(&p_pos_u,  g_pos_u);
    cudaGetSymbolAddress(&p_adj_m,  g_adj_m);
    cudaGetSymbolAddress(&p_adj_u,  g_adj_u);
    cudaGetSymbolAddress(&p_bsum_m, g_bsum_m);
    cudaGetSymbolAddress(&p_bsum_u, g_bsum_u);
    cudaGetSymbolAddress(&p_cvec,   g_cvec);
    cudaGetSymbolAddress(&p_bvec,   g_bvec_u1);
    cudaGetSymbolAddress(&p_wpool,  g_wpool);

    float* movie_x = (float*)p_movie_x;
    float* movie_h = (float*)p_movie_h;
    float* aggM    = (float*)p_aggM;
    float* user_h  = (float*)p_user_h;
    float* user_o  = (float*)p_user_o;
    float* aggU    = (float*)p_aggU;
    float* aggU2   = (float*)p_aggU2;
    int* cnt_m = (int*)p_cnt_m; int* cnt_u = (int*)p_cnt_u;
    int* off_m = (int*)p_off_m; int* off_u = (int*)p_off_u;
    int* pos_m = (int*)p_pos_m; int* pos_u = (int*)p_pos_u;
    int* adj_m = (int*)p_adj_m; int* adj_u = (int*)p_adj_u;
    int* bsum_m = (int*)p_bsum_m; int* bsum_u = (int*)p_bsum_u;
    float* cvec = (float*)p_cvec; float* bvec_u1 = (float*)p_bvec;
    __nv_bfloat16* wpool = (__nv_bfloat16*)p_wpool;

    cudaFuncSetAttribute(gemm_mma2_kernel<false, false, false>, cudaFuncAttributeMaxDynamicSharedMemorySize, SM2_TOTAL);
    cudaFuncSetAttribute(gemm_mma2_kernel<true,  false, false>, cudaFuncAttributeMaxDynamicSharedMemorySize, SM2_TOTAL);
    cudaFuncSetAttribute(gemm_mma2_kernel<true,  false, true >, cudaFuncAttributeMaxDynamicSharedMemorySize, SM2_TOTAL);
    cudaFuncSetAttribute(gemm_mma2_kernel<false, true,  false>, cudaFuncAttributeMaxDynamicSharedMemorySize, SM2_TOTAL);

    const int nbM = (NMc + 1023) / 1024;
    const int nbU = (NUc + 1023) / 1024;
    const int gM = (NMc + 63) / 64;     // 1250
    const int gU = (NUc + 63) / 64;     // 3125

    cudaStream_t s1 = g_sr.s1;

    // ======== fork ========
    cudaEventRecord(g_sr.eFork, 0);
    cudaStreamWaitEvent(s1, g_sr.eFork, 0);

    // ---- s1: CSR build branch (L2/atomic-bound) ----
    zero_int_kernel<<<(NMc + 255) / 256, 256, 0, s1>>>(cnt_m, NMc);
    zero_int_kernel<<<(NUc + 255) / 256, 256, 0, s1>>>(cnt_u, NUc);
    hist_kernel<<<2048, 256, 0, s1>>>(edge_src, edge_dst, cnt_u, cnt_m, Ec);
    cudaEventRecord(g_sr.eHist, s1);
    scan_block_kernel<<<nbM, 1024, 0, s1>>>(cnt_m, off_m, bsum_m, NMc);
    scan_sums_kernel<<<1, 32, 0, s1>>>(bsum_m, nbM);
    scan_add_kernel<<<nbM, 1024, 0, s1>>>(off_m, bsum_m, NMc);
    scan_block_kernel<<<nbU, 1024, 0, s1>>>(cnt_u, off_u, bsum_u, NUc);
    scan_sums_kernel<<<1, 32, 0, s1>>>(bsum_u, nbU);
    scan_add_kernel<<<nbU, 1024, 0, s1>>>(off_u, bsum_u, NUc);
    copy_int_kernel<<<(NMc + 255) / 256, 256, 0, s1>>>(pos_m, off_m, NMc);
    copy_int_kernel<<<(NUc + 255) / 256, 256, 0, s1>>>(pos_u, off_u, NUc);
    place_kernel<<<2048, 256, 0, s1>>>(edge_src, edge_dst, pos_u, pos_m, adj_u, adj_m, Ec);
    cudaEventRecord(g_sr.eCsr, s1);

    // ---- s0: weight conversions + movie feature GEMM (tensor-bound) ----
    wconv_kernel<<<(FDc * Hc + 255) / 256, 256>>>(Wm,     wpool + OFF_WM,    FDc * Hc);
    wconv_kernel<<<(Hc * Hc + 255) / 256, 256>>>(Wl1_mu, wpool + OFF_WL1MU, Hc * Hc);
    wconv_kernel<<<(Hc * Hc + 255) / 256, 256>>>(Wr1_um, wpool + OFF_WR1UM, Hc * Hc);
    wconv_kernel<<<(Hc * Hc + 255) / 256, 256>>>(Wl2_um, wpool + OFF_WL2UM, Hc * Hc);
    wconv_kernel<<<(Hc * Hc + 255) / 256, 256>>>(Wr2_um, wpool + OFF_WR2UM, Hc * Hc);
    wconv_kernel<<<(Hc * Hc + 255) / 256, 256>>>(Wl2_mu, wpool + OFF_WL2MU, Hc * Hc);
    wconv_kernel<<<(Hc * Hc + 255) / 256, 256>>>(Wr2_mu, wpool + OFF_WR2MU, Hc * Hc);
    prevec_kernel<<<1, Hc>>>(user_init, Wl1_um, Wr1_mu, bl1_mu, cvec, bvec_u1);

    // movie_x = movie_feats @ Wm + bm
    gemm_mma2_kernel<false, false, false><<<gM, 256, SM2_TOTAL>>>(
        movie_feats, wpool + OFF_WM, FDc, bm, nullptr, nullptr, movie_x, NMc);
    cudaEventRecord(g_sr.eG1, 0);

    // s0: conv1 movie side (needs cnt_m from hist): movie_h = relu(movie_x@Wr1_um + bl1_um + flag*cvec)
    cudaStreamWaitEvent(0, g_sr.eHist, 0);
    gemm_mma2_kernel<true, false, true><<<gM, 256, SM2_TOTAL>>>(
        movie_x, wpool + OFF_WR1UM, Hc, bl1_um, cvec, cnt_m, movie_h, NMc);
    cudaEventRecord(g_sr.eMH, 0);

    // ---- s1 chain A: agg_u1 -> user_h GEMM -> aggM -> movie_o pass2 ----
    cudaStreamWaitEvent(s1, g_sr.eG1, 0);
    agg_mean_kernel<<<(NUc * 32 + 255) / 256, 256, 0, s1>>>(off_u, adj_u, movie_x, aggU, NUc);
    gemm_mma2_kernel<true, false, false><<<gU, 256, SM2_TOTAL, s1>>>(
        aggU, wpool + OFF_WL1MU, Hc, bvec_u1, nullptr, nullptr, user_h, NUc);
    cudaEventRecord(g_sr.eUH, s1);
    agg_mean_kernel<<<(NMc * 32 + 255) / 256, 256, 0, s1>>>(off_m, adj_m, user_h, aggM, NMc);

    // ---- s0 chain B: aggU2 -> user_o pass1 -> movie_o pass1 -> (wait user_h) user_o pass2 ----
    cudaStreamWaitEvent(0, g_sr.eCsr, 0);
    agg_mean_kernel<<<(NUc * 32 + 255) / 256, 256>>>(off_u, adj_u, movie_h, aggU2, NUc);
    // user_o pass1: aggU2 @ Wl2_mu + bl2_mu   (does NOT wait for user_h)
    gemm_mma2_kernel<false, false, false><<<gU, 256, SM2_TOTAL>>>(
        aggU2, wpool + OFF_WL2MU, Hc, bl2_mu, nullptr, nullptr, user_o, NUc);
    // movie_o pass1: movie_h @ Wr2_um + bl2_um  (movie_h in-stream; aggM not needed yet)
    gemm_mma2_kernel<false, false, false><<<gM, 256, SM2_TOTAL>>>(
        movie_h, wpool + OFF_WR2UM, Hc, bl2_um, nullptr, nullptr, movie_x, NMc);
    cudaEventRecord(g_sr.eMO1, 0);
    // user_o pass2: += user_h @ Wr2_mu
    cudaStreamWaitEvent(0, g_sr.eUH, 0);
    gemm_mma2_kernel<false, true, false><<<gU, 256, SM2_TOTAL>>>(
        user_h, wpool + OFF_WR2MU, Hc, nullptr, nullptr, nullptr, user_o, NUc);

    // ---- s1: movie_o pass2: += aggM @ Wl2_um (after aggM in-stream and movie_o pass1) ----
    cudaStreamWaitEvent(s1, g_sr.eMO1, 0);
    gemm_mma2_kernel<false, true, false><<<gM, 256, SM2_TOTAL, s1>>>(
        aggM, wpool + OFF_WL2UM, Hc, nullptr, nullptr, nullptr, movie_x, NMc);
    cudaEventRecord(g_sr.eMO, s1);

    // ---- join + dot ----
    cudaStreamWaitEvent(0, g_sr.eMO, 0);
    dot_kernel<<<(ELc * 32 + 255) / 256, 256>>>(lbl_user, lbl_movie, user_o, movie_x, out, ELc);
}

// round 13
// speedup vs baseline: 1.0315x; 1.0191x over previous
#include <cuda_runtime.h>
#include <cuda_bf16.h>
#include <cuda_fp16.h>
#include <cstdint>

// Problem-size constants (fixed by the dataset)
#define NUc 200000
#define NMc 80000
#define Ec  2000000
#define ELc 500000
#define Hc  128
#define FDc 512

// ---------------- scratch (static device allocations; no cudaMalloc) ----------------
__device__ float g_movie_x[NMc * Hc];   // movie_x; later reused as movie_o
__device__ float g_movie_h[NMc * Hc];
__device__ float g_aggM  [NMc * Hc];
__device__ float g_user_h[NUc * Hc];
__device__ float g_user_o[NUc * Hc];
__device__ float g_aggU  [NUc * Hc];    // conv1 user aggregation
__device__ float g_aggU2 [NUc * Hc];    // conv2 user aggregation

// fp16 shadow tables for gather-side consumers (halves agg read traffic; 10-bit mantissa)
__device__ __half g_movie_x16[NMc * Hc];
__device__ __half g_movie_h16[NMc * Hc];
__device__ __half g_user_h16[NUc * Hc];

__device__ int g_cnt_m[NMc];
__device__ int g_cnt_u[NUc];
__device__ int g_off_m[NMc + 1];
__device__ int g_off_u[NUc + 1];
__device__ int g_pos_m[NMc];
__device__ int g_pos_u[NUc];
__device__ int g_adj_m[Ec];             // user ids grouped by movie
__device__ int g_adj_u[Ec];             // movie ids grouped by user
__device__ int g_bsum_m[256];
__device__ int g_bsum_u[256];
__device__ float g_cvec[Hc];            // u0 @ Wl1_um
__device__ float g_bvec_u1[Hc];         // bl1_mu + u0 @ Wr1_mu

// bf16 hi/lo weight pool: [hi K*128][lo K*128] per matrix
#define OFF_WM     0
#define OFF_WL1MU  131072
#define OFF_WR1UM  163840
#define OFF_WL2UM  196608
#define OFF_WR2UM  229376
#define OFF_WL2MU  262144
#define OFF_WR2MU  294912
__device__ __nv_bfloat16 g_wpool[327680];

// ---------------- host-side stream/event resources (created pre-main) ----------------
struct StreamRes {
    cudaStream_t s1;
    cudaEvent_t eFork, eHist, eCsr, eG1, eMH, eUH, eMO;
    StreamRes() {
        cudaStreamCreateWithFlags(&s1, cudaStreamNonBlocking);
        cudaEventCreateWithFlags(&eFork, cudaEventDisableTiming);
        cudaEventCreateWithFlags(&eHist, cudaEventDisableTiming);
        cudaEventCreateWithFlags(&eCsr,  cudaEventDisableTiming);
        cudaEventCreateWithFlags(&eG1,   cudaEventDisableTiming);
        cudaEventCreateWithFlags(&eMH,   cudaEventDisableTiming);
        cudaEventCreateWithFlags(&eUH,   cudaEventDisableTiming);
        cudaEventCreateWithFlags(&eMO,   cudaEventDisableTiming);
    }
};
static StreamRes g_sr;

// ---------------- small utility kernels ----------------
__global__ void zero_int_kernel(int* p, int n) {
    int i = blockIdx.x * blockDim.x + threadIdx.x;
    if (i < n) p[i] = 0;
}
__global__ void copy_int_kernel(int* dst, const int* src, int n) {
    int i = blockIdx.x * blockDim.x + threadIdx.x;
    if (i < n) dst[i] = src[i];
}
__global__ void hist_kernel(const int* __restrict__ src, const int* __restrict__ dst,
                            int* cnt_u, int* cnt_m, int n) {
    for (int e = blockIdx.x * blockDim.x + threadIdx.x; e < n; e += gridDim.x * blockDim.x) {
        atomicAdd(&cnt_m[dst[e]], 1);
        atomicAdd(&cnt_u[src[e]], 1);
    }
}
__global__ void place_kernel(const int* __restrict__ src, const int* __restrict__ dst,
                             int* pos_u, int* pos_m, int* adj_u, int* adj_m, int n) {
    for (int e = blockIdx.x * blockDim.x + threadIdx.x; e < n; e += gridDim.x * blockDim.x) {
        int s = src[e], d = dst[e];
        int p = atomicAdd(&pos_m[d], 1);
        adj_m[p] = s;
        int q = atomicAdd(&pos_u[s], 1);
        adj_u[q] = d;
    }
}
__global__ void scan_block_kernel(const int* __restrict__ cnt, int* out, int* bsums, int n) {
    __shared__ int sh[1024];
    int tid = threadIdx.x;
    int i = blockIdx.x * 1024 + tid;
    int v = (i < n) ? cnt[i] : 0;
    sh[tid] = v;
    __syncthreads();
    #pragma unroll
    for (int off = 1; off < 1024; off <<= 1) {
        int t = (tid >= off) ? sh[tid - off] : 0;
        __syncthreads();
        sh[tid] += t;
        __syncthreads();
    }
    if (i < n) out[i + 1] = sh[tid];
    if (tid == 1023) bsums[blockIdx.x] = sh[1023];
}
__global__ void scan_sums_kernel(int* bsums, int nb) {
    if (threadIdx.x == 0 && blockIdx.x == 0) {
        int acc = 0;
        for (int b = 0; b < nb; b++) { int v = bsums[b]; bsums[b] = acc; acc += v; }
    }
}
__global__ void scan_add_kernel(int* out, const int* __restrict__ bsums, int n) {
    int i = blockIdx.x * 1024 + threadIdx.x;
    if (i < n) out[i + 1] += bsums[blockIdx.x];
    if (i == 0) out[0] = 0;
}
__global__ void prevec_kernel(const float* __restrict__ u0,
                              const float* __restrict__ Wl1um,
                              const float* __restrict__ Wr1mu,
                              const float* __restrict__ bl1mu,
                              float* cvec, float* bvec) {
    int j = threadIdx.x;
    float c = 0.f, r = 0.f;
    for (int k = 0; k < Hc; k++) {
        float u = u0[k];
        c += u * Wl1um[k * Hc + j];
        r += u * Wr1mu[k * Hc + j];
    }
    cvec[j] = c;
    bvec[j] = bl1mu[j] + r;
}

__device__ __forceinline__ float bf_rn(float v) {
    return __bfloat162float(__float2bfloat16_rn(v));
}
// weight pre-conversion: out[0..n) = hi(bf16), out[n..2n) = lo(bf16)
__global__ void wconv_kernel(const float* __restrict__ W, __nv_bfloat16* out, int n) {
    int i = blockIdx.x * blockDim.x + threadIdx.x;
    if (i < n) {
        float w = W[i];
        float h = bf_rn(w);
        out[i] = __float2bfloat16_rn(h);
        out[n + i] = __float2bfloat16_rn(w - h);
    }
}

// ---------------- scatter-mean from fp16 table: one warp per destination node ----------------
__global__ void agg_mean16_kernel(const int* __restrict__ off, const int* __restrict__ adj,
                                  const __half* __restrict__ X, float* __restrict__ out, int n) {
    int w = (blockIdx.x * blockDim.x + threadIdx.x) >> 5;
    int lane = threadIdx.x & 31;
    if (w >= n) return;
    int s = off[w], e = off[w + 1];
    float4 acc = make_float4(0.f, 0.f, 0.f, 0.f);
    int i = s;
    for (; i + 1 < e; i += 2) {
        int j0 = adj[i], j1 = adj[i + 1];
        uint2 u0 = *(const uint2*)(X + (size_t)j0 * Hc + lane * 4);
        uint2 u1 = *(const uint2*)(X + (size_t)j1 * Hc + lane * 4);
        float2 a0 = __half22float2(*reinterpret_cast<__half2*>(&u0.x));
        float2 a1 = __half22float2(*reinterpret_cast<__half2*>(&u0.y));
        float2 b0 = __half22float2(*reinterpret_cast<__half2*>(&u1.x));
        float2 b1 = __half22float2(*reinterpret_cast<__half2*>(&u1.y));
        acc.x += a0.x + b0.x; acc.y += a0.y + b0.y;
        acc.z += a1.x + b1.x; acc.w += a1.y + b1.y;
    }
    if (i < e) {
        int j = adj[i];
        uint2 u0 = *(const uint2*)(X + (size_t)j * Hc + lane * 4);
        float2 a0 = __half22float2(*reinterpret_cast<__half2*>(&u0.x));
        float2 a1 = __half22float2(*reinterpret_cast<__half2*>(&u0.y));
        acc.x += a0.x; acc.y += a0.y; acc.z += a1.x; acc.w += a1.y;
    }
    int cnt = e - s;
    float inv = 1.0f / (float)(cnt > 0 ? cnt : 1);
    acc.x *= inv; acc.y *= inv; acc.z *= inv; acc.w *= inv;
    *(float4*)(out + (size_t)w * Hc + lane * 4) = acc;
}

// ---------------- mma.sync bf16 helpers ----------------
__device__ __forceinline__ void ldm_x4(uint32_t& r0, uint32_t& r1, uint32_t& r2, uint32_t& r3, uint32_t addr) {
    asm volatile("ldmatrix.sync.aligned.m8n8.x4.shared.b16 {%0,%1,%2,%3}, [%4];"
                 : "=r"(r0), "=r"(r1), "=r"(r2), "=r"(r3) : "r"(addr));
}
__device__ __forceinline__ void ldm_x4_t(uint32_t& r0, uint32_t& r1, uint32_t& r2, uint32_t& r3, uint32_t addr) {
    asm volatile("ldmatrix.sync.aligned.m8n8.x4.trans.shared.b16 {%0,%1,%2,%3}, [%4];"
                 : "=r"(r0), "=r"(r1), "=r"(r2), "=r"(r3) : "r"(addr));
}
__device__ __forceinline__ void mma_bf16(float* c, const uint32_t* a, uint32_t b0, uint32_t b1) {
    asm volatile(
        "mma.sync.aligned.m16n8k16.row.col.f32.bf16.bf16.f32 "
        "{%0,%1,%2,%3}, {%4,%5,%6,%7}, {%8,%9}, {%0,%1,%2,%3};"
        : "+f"(c[0]), "+f"(c[1]), "+f"(c[2]), "+f"(c[3])
        : "r"(a[0]), "r"(a[1]), "r"(a[2]), "r"(a[3]), "r"(b0), "r"(b1));
}
__device__ __forceinline__ uint32_t pack_bf16(float x, float y) {
    uint32_t r;
    asm("cvt.rn.bf16x2.f32 %0, %1, %2;" : "=r"(r) : "f"(y), "f"(x));
    return r;
}
__device__ __forceinline__ uint32_t pack_f16(float x, float y) {
    __half2 h = __floats2half2_rn(x, y);
    return *reinterpret_cast<uint32_t*>(&h);
}

// ---------------- split-bf16 tensor-core GEMM (cp.async B path) ----------------
// C[M,128] = epi( A@W [+ A2@W2] + bias [+ flag*flagvec] ); optional fp16 shadow copy C16.
static constexpr int SMA_STR_BUF = 10240;  // per A buf (2 parts)
static constexpr int SMA_STR_PART = 5120;
static constexpr int SMB_BASE = 20480;
static constexpr int SMB_STR_BUF = 17408;
static constexpr int SMB_STR_PART = 8704;
static constexpr int SM2_TOTAL = 55296;

template<bool RELU, bool DUAL, bool FLAGV>
__global__ void __launch_bounds__(256) gemm_mma2_kernel(
    const float* __restrict__ A,  const __nv_bfloat16* __restrict__ B,  int K,
    const float* __restrict__ A2, const __nv_bfloat16* __restrict__ B2,
    const float* __restrict__ bias,
    const float* __restrict__ flagvec, const int* __restrict__ flags,
    float* __restrict__ C, __half* __restrict__ C16, int M)
{
    extern __shared__ __align__(16) char smem[];

    const int tid = threadIdx.x;
    const int lane = tid & 31;
    const int wid = tid >> 5;
    const int wm = wid & 1;        // 0..1 : 32-row slice
    const int wn = wid >> 1;       // 0..3 : 32-col slice
    const int row0 = blockIdx.x * 64;

    const uint32_t sBase = (uint32_t)__cvta_generic_to_shared(&smem[0]);

    float acc[2][4][4];
    #pragma unroll
    for (int mi = 0; mi < 2; mi++)
        #pragma unroll
        for (int j = 0; j < 4; j++)
            #pragma unroll
            for (int q = 0; q < 4; q++) acc[mi][j][q] = 0.f;

    const int nk = K / 32;
    const int nchunks = (DUAL ? 2 : 1) * nk;

    float4 av[2];

    auto cp_b = [&](int c, int buf) {
        int s = (DUAL && c >= nk) ? 1 : 0;
        int kt = (s ? c - nk : c) * 32;
        const __nv_bfloat16* Bp = s ? B2 : B;
        #pragma unroll
        for (int p = 0; p < 2; p++)
            #pragma unroll
            for (int r = 0; r < 2; r++) {
                int idx = tid + r * 256;
                int kk = idx >> 4, h8 = idx & 15;
                uint32_t dst = sBase + SMB_BASE + buf * SMB_STR_BUF + p * SMB_STR_PART + kk * 272 + h8 * 16;
                const void* src = Bp + (size_t)p * K * 128 + (size_t)(kt + kk) * 128 + h8 * 8;
                asm volatile("cp.async.cg.shared.global [%0], [%1], 16;" :: "r"(dst), "l"(src));
            }
        asm volatile("cp.async.commit_group;" ::: "memory");
    };
    auto load_a = [&](int c) {
        int s = (DUAL && c >= nk) ? 1 : 0;
        int kt = (s ? c - nk : c) * 32;
        const float* Ap = s ? A2 : A;
        #pragma unroll
        for (int r = 0; r < 2; r++) {
            int idx = tid + r * 256;
            int m = idx >> 3, c4 = idx & 7;
            int row = row0 + m;
            av[r] = (row < M) ? *(const float4*)(Ap + (size_t)row * K + kt + c4 * 4)
                              : make_float4(0.f, 0.f, 0.f, 0.f);
        }
    };
    auto sts_a = [&](int buf) {
        #pragma unroll
        for (int r = 0; r < 2; r++) {
            int idx = tid + r * 256;
            int m = idx >> 3, c4 = idx & 7;
            float hx = bf_rn(av[r].x), hy = bf_rn(av[r].y);
            float hz = bf_rn(av[r].z), hw = bf_rn(av[r].w);
            uint2 hi, lo;
            hi.x = pack_bf16(hx, hy);
            hi.y = pack_bf16(hz, hw);
            lo.x = pack_bf16(av[r].x - hx, av[r].y - hy);
            lo.y = pack_bf16(av[r].z - hz, av[r].w - hw);
            int off = buf * SMA_STR_BUF + m * 80 + c4 * 8;
            *(uint2*)(&smem[off]) = hi;
            *(uint2*)(&smem[off + SMA_STR_PART]) = lo;
        }
    };

    cp_b(0, 0);
    load_a(0);
    sts_a(0);
    asm volatile("cp.async.wait_group 0;" ::: "memory");
    __syncthreads();

    for (int c = 0; c < nchunks; c++) {
        int buf = c & 1;
        if (c + 1 < nchunks) {
            cp_b(c + 1, buf ^ 1);
            load_a(c + 1);
        }

        uint32_t aHi = sBase + buf * SMA_STR_BUF;
        uint32_t aLo = aHi + SMA_STR_PART;
        uint32_t bHi = sBase + SMB_BASE + buf * SMB_STR_BUF;
        uint32_t bLo = bHi + SMB_STR_PART;

        #pragma unroll
        for (int ks = 0; ks < 2; ks++) {
            uint32_t aoff = (uint32_t)((wm * 32 + (lane & 15)) * 80 + ks * 32 + (lane >> 4) * 16);
            uint32_t ah[2][4], al[2][4];
            #pragma unroll
            for (int mi = 0; mi < 2; mi++) {
                ldm_x4(ah[mi][0], ah[mi][1], ah[mi][2], ah[mi][3], aHi + aoff + mi * 16 * 80);
                ldm_x4(al[mi][0], al[mi][1], al[mi][2], al[mi][3], aLo + aoff + mi * 16 * 80);
            }
            uint32_t bh[4][2], bl[4][2];
            #pragma unroll
            for (int p = 0; p < 2; p++) {
                int krow = ks * 16 + ((lane >> 3) & 1) * 8 + (lane & 7);
                int ncol = wn * 32 + p * 16 + (lane >> 4) * 8;
                uint32_t boff = (uint32_t)(krow * 272 + ncol * 2);
                ldm_x4_t(bh[2 * p][0], bh[2 * p][1], bh[2 * p + 1][0], bh[2 * p + 1][1], bHi + boff);
                ldm_x4_t(bl[2 * p][0], bl[2 * p][1], bl[2 * p + 1][0], bl[2 * p + 1][1], bLo + boff);
            }
            #pragma unroll
            for (int mi = 0; mi < 2; mi++)
                #pragma unroll
                for (int j = 0; j < 4; j++)
                    mma_bf16(acc[mi][j], ah[mi], bh[j][0], bh[j][1]);
            #pragma unroll
            for (int mi = 0; mi < 2; mi++)
                #pragma unroll
                for (int j = 0; j < 4; j++)
                    mma_bf16(acc[mi][j], ah[mi], bl[j][0], bl[j][1]);
            #pragma unroll
            for (int mi = 0; mi < 2; mi++)
                #pragma unroll
                for (int j = 0; j < 4; j++)
                    mma_bf16(acc[mi][j], al[mi], bh[j][0], bh[j][1]);
        }

        if (c + 1 < nchunks) {
            sts_a(buf ^ 1);
            asm volatile("cp.async.wait_group 0;" ::: "memory");
            __syncthreads();
        }
    }

    // ---- epilogue ----
    #pragma unroll
    for (int mi = 0; mi < 2; mi++) {
        int rl = row0 + wm * 32 + mi * 16 + (lane >> 2);
        int rh = rl + 8;
        float fl_l = 0.f, fl_h = 0.f;
        if (FLAGV) {
            if (rl < M) fl_l = (flags[rl] > 0) ? 1.f : 0.f;
            if (rh < M) fl_h = (flags[rh] > 0) ? 1.f : 0.f;
        }
        #pragma unroll
        for (int j = 0; j < 4; j++) {
            int col = wn * 32 + j * 8 + (lane & 3) * 2;
            float b0 = __ldg(&bias[col]), b1 = __ldg(&bias[col + 1]);
            float f0 = 0.f, f1 = 0.f;
            if (FLAGV) { f0 = __ldg(&flagvec[col]); f1 = __ldg(&flagvec[col + 1]); }
            float v0 = acc[mi][j][0] + b0;
            float v1 = acc[mi][j][1] + b1;
            float v2 = acc[mi][j][2] + b0;
            float v3 = acc[mi][j][3] + b1;
            if (FLAGV) { v0 += fl_l * f0; v1 += fl_l * f1; v2 += fl_h * f0; v3 += fl_h * f1; }
            if (RELU) {
                v0 = fmaxf(v0, 0.f); v1 = fmaxf(v1, 0.f);
                v2 = fmaxf(v2, 0.f); v3 = fmaxf(v3, 0.f);
            }
            if (rl < M) {
                *(float2*)(C + (size_t)rl * 128 + col) = make_float2(v0, v1);
                if (C16) *(uint32_t*)(C16 + (size_t)rl * 128 + col) = pack_f16(v0, v1);
            }
            if (rh < M) {
                *(float2*)(C + (size_t)rh * 128 + col) = make_float2(v2, v3);
                if (C16) *(uint32_t*)(C16 + (size_t)rh * 128 + col) = pack_f16(v2, v3);
            }
        }
    }
}

// ---------------- final edge-wise dot: one warp per supervision edge ----------------
__global__ void dot_kernel(const int* __restrict__ lu, const int* __restrict__ lm,
                           const float* __restrict__ U, const float* __restrict__ Mo,
                           float* __restrict__ out, int n) {
    int w = (blockIdx.x * blockDim.x + threadIdx.x) >> 5;
    int lane = threadIdx.x & 31;
    if (w >= n) return;
    int u = lu[w], m = lm[w];
    float4 a = *(const float4*)(U  + (size_t)u * Hc + lane * 4);
    float4 b = *(const float4*)(Mo + (size_t)m * Hc + lane * 4);
    float p = a.x * b.x + a.y * b.y + a.z * b.z + a.w * b.w;
    #pragma unroll
    for (int o = 16; o > 0; o >>= 1) p += __shfl_xor_sync(0xFFFFFFFFu, p, o);
    if (lane == 0) out[w] = p;
}

// ---------------- host launcher ----------------
extern "C" void kernel_launch(void* const* d_in, const int* in_sizes, int n_in,
                              void* d_out, int out_size) {
    const float* movie_feats = (const float*)d_in[0];
    const float* user_init   = (const float*)d_in[1];
    const int*   edge_src    = (const int*)d_in[2];
    const int*   edge_dst    = (const int*)d_in[3];
    const int*   lbl_user    = (const int*)d_in[4];
    const int*   lbl_movie   = (const int*)d_in[5];
    int wb = (in_sizes[6] == FDc * Hc) ? 6 : 7;
    const float* Wm     = (const float*)d_in[wb + 0];
    const float* bm     = (const float*)d_in[wb + 1];
    const float* Wl1_um = (const float*)d_in[wb + 2];
    const float* bl1_um = (const float*)d_in[wb + 3];
    const float* Wr1_um = (const float*)d_in[wb + 4];
    const float* Wl1_mu = (const float*)d_in[wb + 5];
    const float* bl1_mu = (const float*)d_in[wb + 6];
    const float* Wr1_mu = (const float*)d_in[wb + 7];
    const float* Wl2_um = (const float*)d_in[wb + 8];
    const float* bl2_um = (const float*)d_in[wb + 9];
    const float* Wr2_um = (const float*)d_in[wb + 10];
    const float* Wl2_mu = (const float*)d_in[wb + 11];
    const float* bl2_mu = (const float*)d_in[wb + 12];
    const float* Wr2_mu = (const float*)d_in[wb + 13];

    float* out = (float*)d_out;

    void *p_movie_x, *p_movie_h, *p_aggM, *p_user_h, *p_user_o, *p_aggU, *p_aggU2;
    void *p_mx16, *p_mh16, *p_uh16;
    void *p_cnt_m, *p_cnt_u, *p_off_m, *p_off_u, *p_pos_m, *p_pos_u;
    void *p_adj_m, *p_adj_u, *p_bsum_m, *p_bsum_u, *p_cvec, *p_bvec, *p_wpool;
    cudaGetSymbolAddress(&p_movie_x, g_movie_x);
    cudaGetSymbolAddress(&p_movie_h, g_movie_h);
    cudaGetSymbolAddress(&p_aggM,   g_aggM);
    cudaGetSymbolAddress(&p_user_h, g_user_h);
    cudaGetSymbolAddress(&p_user_o, g_user_o);
    cudaGetSymbolAddress(&p_aggU,   g_aggU);
    cudaGetSymbolAddress(&p_aggU2,  g_aggU2);
    cudaGetSymbolAddress(&p_mx16,   g_movie_x16);
    cudaGetSymbolAddress(&p_mh16,   g_movie_h16);
    cudaGetSymbolAddress(&p_uh16,   g_user_h16);
    cudaGetSymbolAddress(&p_cnt_m,  g_cnt_m);
    cudaGetSymbolAddress(&p_cnt_u,  g_cnt_u);
    cudaGetSymbolAddress(&p_off_m,  g_off_m);
    cudaGetSymbolAddress(&p_off_u,  g_off_u);
    cudaGetSymbolAddress(&p_pos_m,  g_pos_m);
    cudaGetSymbolAddress(&p_pos_u,  g_pos_u);
    cudaGetSymbolAddress(&p_adj_m,  g_adj_m);
    cudaGetSymbolAddress(&p_adj_u,  g_adj_u);
    cudaGetSymbolAddress(&p_bsum_m, g_bsum_m);
    cudaGetSymbolAddress(&p_bsum_u, g_bsum_u);
    cudaGetSymbolAddress(&p_cvec,   g_cvec);
    cudaGetSymbolAddress(&p_bvec,   g_bvec_u1);
    cudaGetSymbolAddress(&p_wpool,  g_wpool);

    float* movie_x = (float*)p_movie_x;
    float* movie_h = (float*)p_movie_h;
    float* aggM    = (float*)p_aggM;
    float* user_h  = (float*)p_user_h;
    float* user_o  = (float*)p_user_o;
    float* aggU    = (float*)p_aggU;
    float* aggU2   = (float*)p_aggU2;
    __half* mx16 = (__half*)p_mx16;
    __half* mh16 = (__half*)p_mh16;
    __half* uh16 = (__half*)p_uh16;
    int* cnt_m = (int*)p_cnt_m; int* cnt_u = (int*)p_cnt_u;
    int* off_m = (int*)p_off_m; int* off_u = (int*)p_off_u;
    int* pos_m = (int*)p_pos_m; int* pos_u = (int*)p_pos_u;
    int* adj_m = (int*)p_adj_m; int* adj_u = (int*)p_adj_u;
    int* bsum_m = (int*)p_bsum_m; int* bsum_u = (int*)p_bsum_u;
    float* cvec = (float*)p_cvec; float* bvec_u1 = (float*)p_bvec;
    __nv_bfloat16* wpool = (__nv_bfloat16*)p_wpool;

    cudaFuncSetAttribute(gemm_mma2_kernel<false, false, false>, cudaFuncAttributeMaxDynamicSharedMemorySize, SM2_TOTAL);
    cudaFuncSetAttribute(gemm_mma2_kernel<true,  false, false>, cudaFuncAttributeMaxDynamicSharedMemorySize, SM2_TOTAL);
    cudaFuncSetAttribute(gemm_mma2_kernel<true,  false, true >, cudaFuncAttributeMaxDynamicSharedMemorySize, SM2_TOTAL);
    cudaFuncSetAttribute(gemm_mma2_kernel<false, true,  false>, cudaFuncAttributeMaxDynamicSharedMemorySize, SM2_TOTAL);

    const int nbM = (NMc + 1023) / 1024;
    const int nbU = (NUc + 1023) / 1024;
    const int gM = (NMc + 63) / 64;     // 1250
    const int gU = (NUc + 63) / 64;     // 3125

    cudaStream_t s1 = g_sr.s1;

    // ======== fork ========
    cudaEventRecord(g_sr.eFork, 0);
    cudaStreamWaitEvent(s1, g_sr.eFork, 0);

    // ---- s0: wconv(Wm) -> GEMM1 immediately (shortest critical prefix) ----
    wconv_kernel<<<(FDc * Hc + 255) / 256, 256>>>(Wm, wpool + OFF_WM, FDc * Hc);
    gemm_mma2_kernel<false, false, false><<<gM, 256, SM2_TOTAL>>>(
        movie_feats, wpool + OFF_WM, FDc, nullptr, nullptr, bm, nullptr, nullptr, movie_x, mx16, NMc);
    cudaEventRecord(g_sr.eG1, 0);

    // ---- s1: small wconvs + prevec, then CSR build ----
    wconv_kernel<<<(Hc * Hc + 255) / 256, 256, 0, s1>>>(Wl1_mu, wpool + OFF_WL1MU, Hc * Hc);
    wconv_kernel<<<(Hc * Hc + 255) / 256, 256, 0, s1>>>(Wr1_um, wpool + OFF_WR1UM, Hc * Hc);
    wconv_kernel<<<(Hc * Hc + 255) / 256, 256, 0, s1>>>(Wl2_um, wpool + OFF_WL2UM, Hc * Hc);
    wconv_kernel<<<(Hc * Hc + 255) / 256, 256, 0, s1>>>(Wr2_um, wpool + OFF_WR2UM, Hc * Hc);
    wconv_kernel<<<(Hc * Hc + 255) / 256, 256, 0, s1>>>(Wl2_mu, wpool + OFF_WL2MU, Hc * Hc);
    wconv_kernel<<<(Hc * Hc + 255) / 256, 256, 0, s1>>>(Wr2_mu, wpool + OFF_WR2MU, Hc * Hc);
    prevec_kernel<<<1, Hc, 0, s1>>>(user_init, Wl1_um, Wr1_mu, bl1_mu, cvec, bvec_u1);

    zero_int_kernel<<<(NMc + 255) / 256, 256, 0, s1>>>(cnt_m, NMc);
    zero_int_kernel<<<(NUc + 255) / 256, 256, 0, s1>>>(cnt_u, NUc);
    hist_kernel<<<2048, 256, 0, s1>>>(edge_src, edge_dst, cnt_u, cnt_m, Ec);
    cudaEventRecord(g_sr.eHist, s1);
    scan_block_kernel<<<nbM, 1024, 0, s1>>>(cnt_m, off_m, bsum_m, NMc);
    scan_sums_kernel<<<1, 32, 0, s1>>>(bsum_m, nbM);
    scan_add_kernel<<<nbM, 1024, 0, s1>>>(off_m, bsum_m, NMc);
    scan_block_kernel<<<nbU, 1024, 0, s1>>>(cnt_u, off_u, bsum_u, NUc);
    scan_sums_kernel<<<1, 32, 0, s1>>>(bsum_u, nbU);
    scan_add_kernel<<<nbU, 1024, 0, s1>>>(off_u, bsum_u, NUc);
    copy_int_kernel<<<(NMc + 255) / 256, 256, 0, s1>>>(pos_m, off_m, NMc);
    copy_int_kernel<<<(NUc + 255) / 256, 256, 0, s1>>>(pos_u, off_u, NUc);
    place_kernel<<<2048, 256, 0, s1>>>(edge_src, edge_dst, pos_u, pos_m, adj_u, adj_m, Ec);
    cudaEventRecord(g_sr.eCsr, s1);

    // ---- s0 chain B: movie_h -> aggU2 -> user_o ----
    cudaStreamWaitEvent(0, g_sr.eHist, 0);   // cnt_m + wconv(Wr1_um) + prevec ready
    gemm_mma2_kernel<true, false, true><<<gM, 256, SM2_TOTAL>>>(
        movie_x, wpool + OFF_WR1UM, Hc, nullptr, nullptr, bl1_um, cvec, cnt_m, movie_h, mh16, NMc);
    cudaEventRecord(g_sr.eMH, 0);

    // ---- s1 chain A: agg_u1(fp16) -> user_h GEMM -> aggM(fp16) -> movie_o ----
    cudaStreamWaitEvent(s1, g_sr.eG1, 0);    // movie_x ready (CSR in-stream)
    agg_mean16_kernel<<<(NUc * 32 + 255) / 256, 256, 0, s1>>>(off_u, adj_u, mx16, aggU, NUc);
    gemm_mma2_kernel<true, false, false><<<gU, 256, SM2_TOTAL, s1>>>(
        aggU, wpool + OFF_WL1MU, Hc, nullptr, nullptr, bvec_u1, nullptr, nullptr, user_h, uh16, NUc);
    cudaEventRecord(g_sr.eUH, s1);
    agg_mean16_kernel<<<(NMc * 32 + 255) / 256, 256, 0, s1>>>(off_m, adj_m, uh16, aggM, NMc);
    cudaStreamWaitEvent(s1, g_sr.eMH, 0);
    gemm_mma2_kernel<false, true, false><<<gM, 256, SM2_TOTAL, s1>>>(
        aggM, wpool + OFF_WL2UM, Hc, movie_h, wpool + OFF_WR2UM, bl2_um, nullptr, nullptr, movie_x, nullptr, NMc);
    cudaEventRecord(g_sr.eMO, s1);

    // ---- s0: aggU2(fp16, needs movie_h in-stream + CSR) -> user_o ----
    cudaStreamWaitEvent(0, g_sr.eCsr, 0);
    agg_mean16_kernel<<<(NUc * 32 + 255) / 256, 256>>>(off_u, adj_u, mh16, aggU2, NUc);
    cudaStreamWaitEvent(0, g_sr.eUH, 0);
    gemm_mma2_kernel<false, true, false><<<gU, 256, SM2_TOTAL>>>(
        aggU2, wpool + OFF_WL2MU, Hc, user_h, wpool + OFF_WR2MU, bl2_mu, nullptr, nullptr, user_o, nullptr, NUc);

    // ---- join + dot ----
    cudaStreamWaitEvent(0, g_sr.eMO, 0);
    dot_kernel<<<(ELc * 32 + 255) / 256, 256>>>(lbl_user, lbl_movie, user_o, movie_x, out, ELc);
}

// round 14
// speedup vs baseline: 1.0386x; 1.0068x over previous
#include <cuda_runtime.h>
#include <cuda_bf16.h>
#include <cstdint>

// Problem-size constants (fixed by the dataset)
#define NUc 200000
#define NMc 80000
#define Ec  2000000
#define ELc 500000
#define Hc  128
#define FDc 512

// ---------------- scratch (static device allocations; no cudaMalloc) ----------------
__device__ float g_movie_x[NMc * Hc];   // movie_x; later reused as movie_o
__device__ float g_movie_h[NMc * Hc];
__device__ float g_aggM  [NMc * Hc];
__device__ float g_user_h[NUc * Hc];
__device__ float g_user_o[NUc * Hc];
__device__ float g_aggU  [NUc * Hc];    // conv1 user aggregation
__device__ float g_aggU2 [NUc * Hc];    // conv2 user aggregation

__device__ int g_cnt_m[NMc];
__device__ int g_cnt_u[NUc];
__device__ int g_off_m[NMc + 1];
__device__ int g_off_u[NUc + 1];
__device__ int g_pos_m[NMc];
__device__ int g_pos_u[NUc];
__device__ int g_adj_m[Ec];             // user ids grouped by movie
__device__ int g_adj_u[Ec];             // movie ids grouped by user
__device__ int g_bsum_m[256];
__device__ int g_bsum_u[256];
__device__ float g_cvec[Hc];            // u0 @ Wl1_um
__device__ float g_bvec_u1[Hc];         // bl1_mu + u0 @ Wr1_mu

// bf16 hi/lo weight pool: [hi K*128][lo K*128] per matrix
#define OFF_WM     0
#define OFF_WL1MU  131072
#define OFF_WR1UM  163840
#define OFF_WL2UM  196608
#define OFF_WR2UM  229376
#define OFF_WL2MU  262144
#define OFF_WR2MU  294912
__device__ __nv_bfloat16 g_wpool[327680];

// ---------------- host-side stream/event resources (created pre-main) ----------------
struct StreamRes {
    cudaStream_t s1;
    cudaEvent_t eFork, eHist, eCsr, eG1, eMH, eUH, eMO;
    StreamRes() {
        cudaStreamCreateWithFlags(&s1, cudaStreamNonBlocking);
        cudaEventCreateWithFlags(&eFork, cudaEventDisableTiming);
        cudaEventCreateWithFlags(&eHist, cudaEventDisableTiming);
        cudaEventCreateWithFlags(&eCsr,  cudaEventDisableTiming);
        cudaEventCreateWithFlags(&eG1,   cudaEventDisableTiming);
        cudaEventCreateWithFlags(&eMH,   cudaEventDisableTiming);
        cudaEventCreateWithFlags(&eUH,   cudaEventDisableTiming);
        cudaEventCreateWithFlags(&eMO,   cudaEventDisableTiming);
    }
};
static StreamRes g_sr;

// ---------------- small utility kernels ----------------
__global__ void zero_int_kernel(int* p, int n) {
    int i = blockIdx.x * blockDim.x + threadIdx.x;
    if (i < n) p[i] = 0;
}
__global__ void copy_int_kernel(int* dst, const int* src, int n) {
    int i = blockIdx.x * blockDim.x + threadIdx.x;
    if (i < n) dst[i] = src[i];
}
__global__ void hist_kernel(const int* __restrict__ src, const int* __restrict__ dst,
                            int* cnt_u, int* cnt_m, int n) {
    for (int e = blockIdx.x * blockDim.x + threadIdx.x; e < n; e += gridDim.x * blockDim.x) {
        atomicAdd(&cnt_m[dst[e]], 1);
        atomicAdd(&cnt_u[src[e]], 1);
    }
}
__global__ void place_kernel(const int* __restrict__ src, const int* __restrict__ dst,
                             int* pos_u, int* pos_m, int* adj_u, int* adj_m, int n) {
    for (int e = blockIdx.x * blockDim.x + threadIdx.x; e < n; e += gridDim.x * blockDim.x) {
        int s = src[e], d = dst[e];
        int p = atomicAdd(&pos_m[d], 1);
        adj_m[p] = s;
        int q = atomicAdd(&pos_u[s], 1);
        adj_u[q] = d;
    }
}
__global__ void scan_block_kernel(const int* __restrict__ cnt, int* out, int* bsums, int n) {
    __shared__ int sh[1024];
    int tid = threadIdx.x;
    int i = blockIdx.x * 1024 + tid;
    int v = (i < n) ? cnt[i] : 0;
    sh[tid] = v;
    __syncthreads();
    #pragma unroll
    for (int off = 1; off < 1024; off <<= 1) {
        int t = (tid >= off) ? sh[tid - off] : 0;
        __syncthreads();
        sh[tid] += t;
        __syncthreads();
    }
    if (i < n) out[i + 1] = sh[tid];
    if (tid == 1023) bsums[blockIdx.x] = sh[1023];
}
__global__ void scan_sums_kernel(int* bsums, int nb) {
    if (threadIdx.x == 0 && blockIdx.x == 0) {
        int acc = 0;
        for (int b = 0; b < nb; b++) { int v = bsums[b]; bsums[b] = acc; acc += v; }
    }
}
__global__ void scan_add_kernel(int* out, const int* __restrict__ bsums, int n) {
    int i = blockIdx.x * 1024 + threadIdx.x;
    if (i < n) out[i + 1] += bsums[blockIdx.x];
    if (i == 0) out[0] = 0;
}
__global__ void prevec_kernel(const float* __restrict__ u0,
                              const float* __restrict__ Wl1um,
                              const float* __restrict__ Wr1mu,
                              const float* __restrict__ bl1mu,
                              float* cvec, float* bvec) {
    int j = threadIdx.x;
    float c = 0.f, r = 0.f;
    for (int k = 0; k < Hc; k++) {
        float u = u0[k];
        c += u * Wl1um[k * Hc + j];
        r += u * Wr1mu[k * Hc + j];
    }
    cvec[j] = c;
    bvec[j] = bl1mu[j] + r;
}

__device__ __forceinline__ float bf_rn(float v) {
    return __bfloat162float(__float2bfloat16_rn(v));
}
// weight pre-conversion: out[0..n) = hi(bf16), out[n..2n) = lo(bf16)
__global__ void wconv_kernel(const float* __restrict__ W, __nv_bfloat16* out, int n) {
    int i = blockIdx.x * blockDim.x + threadIdx.x;
    if (i < n) {
        float w = W[i];
        float h = bf_rn(w);
        out[i] = __float2bfloat16_rn(h);
        out[n + i] = __float2bfloat16_rn(w - h);
    }
}

// ---------------- scatter-mean via CSR gather: one warp per destination node ----------------
// Unroll-4 neighbor loop: 4 independent LDG.128 in flight (MLP=4) to cut exposed latency.
__global__ void agg_mean_kernel(const int* __restrict__ off, const int* __restrict__ adj,
                                const float* __restrict__ X, float* __restrict__ out, int n) {
    int w = (blockIdx.x * blockDim.x + threadIdx.x) >> 5;
    int lane = threadIdx.x & 31;
    if (w >= n) return;
    int s = off[w], e = off[w + 1];
    float4 acc0 = make_float4(0.f, 0.f, 0.f, 0.f);
    float4 acc1 = make_float4(0.f, 0.f, 0.f, 0.f);
    int i = s;
    for (; i + 3 < e; i += 4) {
        int j0 = adj[i], j1 = adj[i + 1], j2 = adj[i + 2], j3 = adj[i + 3];
        float4 v0 = *(const float4*)(X + (size_t)j0 * Hc + lane * 4);
        float4 v1 = *(const float4*)(X + (size_t)j1 * Hc + lane * 4);
        float4 v2 = *(const float4*)(X + (size_t)j2 * Hc + lane * 4);
        float4 v3 = *(const float4*)(X + (size_t)j3 * Hc + lane * 4);
        acc0.x += v0.x + v1.x; acc0.y += v0.y + v1.y;
        acc0.z += v0.z + v1.z; acc0.w += v0.w + v1.w;
        acc1.x += v2.x + v3.x; acc1.y += v2.y + v3.y;
        acc1.z += v2.z + v3.z; acc1.w += v2.w + v3.w;
    }
    for (; i < e; i++) {
        int j = adj[i];
        float4 v = *(const float4*)(X + (size_t)j * Hc + lane * 4);
        acc0.x += v.x; acc0.y += v.y; acc0.z += v.z; acc0.w += v.w;
    }
    acc0.x += acc1.x; acc0.y += acc1.y; acc0.z += acc1.z; acc0.w += acc1.w;
    int cnt = e - s;
    float inv = 1.0f / (float)(cnt > 0 ? cnt : 1);
    acc0.x *= inv; acc0.y *= inv; acc0.z *= inv; acc0.w *= inv;
    *(float4*)(out + (size_t)w * Hc + lane * 4) = acc0;
}

// ---------------- mma.sync bf16 helpers ----------------
__device__ __forceinline__ void ldm_x4(uint32_t& r0, uint32_t& r1, uint32_t& r2, uint32_t& r3, uint32_t addr) {
    asm volatile("ldmatrix.sync.aligned.m8n8.x4.shared.b16 {%0,%1,%2,%3}, [%4];"
                 : "=r"(r0), "=r"(r1), "=r"(r2), "=r"(r3) : "r"(addr));
}
__device__ __forceinline__ void ldm_x4_t(uint32_t& r0, uint32_t& r1, uint32_t& r2, uint32_t& r3, uint32_t addr) {
    asm volatile("ldmatrix.sync.aligned.m8n8.x4.trans.shared.b16 {%0,%1,%2,%3}, [%4];"
                 : "=r"(r0), "=r"(r1), "=r"(r2), "=r"(r3) : "r"(addr));
}
__device__ __forceinline__ void mma_bf16(float* c, const uint32_t* a, uint32_t b0, uint32_t b1) {
    asm volatile(
        "mma.sync.aligned.m16n8k16.row.col.f32.bf16.bf16.f32 "
        "{%0,%1,%2,%3}, {%4,%5,%6,%7}, {%8,%9}, {%0,%1,%2,%3};"
        : "+f"(c[0]), "+f"(c[1]), "+f"(c[2]), "+f"(c[3])
        : "r"(a[0]), "r"(a[1]), "r"(a[2]), "r"(a[3]), "r"(b0), "r"(b1));
}
__device__ __forceinline__ uint32_t pack_bf16(float x, float y) {
    uint32_t r;
    asm("cvt.rn.bf16x2.f32 %0, %1, %2;" : "=r"(r) : "f"(y), "f"(x));
    return r;
}

// ---------------- split-bf16 tensor-core GEMM (cp.async B path) ----------------
// C[M,128] = epi( A@W [+ A2@W2] + bias [+ flag*flagvec] )
static constexpr int SMA_STR_BUF = 10240;  // per A buf (2 parts)
static constexpr int SMA_STR_PART = 5120;
static constexpr int SMB_BASE = 20480;
static constexpr int SMB_STR_BUF = 17408;
static constexpr int SMB_STR_PART = 8704;
static constexpr int SM2_TOTAL = 55296;

template<bool RELU, bool DUAL, bool FLAGV>
__global__ void __launch_bounds__(256) gemm_mma2_kernel(
    const float* __restrict__ A,  const __nv_bfloat16* __restrict__ B,  int K,
    const float* __restrict__ A2, const __nv_bfloat16* __restrict__ B2,
    const float* __restrict__ bias,
    const float* __restrict__ flagvec, const int* __restrict__ flags,
    float* __restrict__ C, int M)
{
    extern __shared__ __align__(16) char smem[];

    const int tid = threadIdx.x;
    const int lane = tid & 31;
    const int wid = tid >> 5;
    const int wm = wid & 1;        // 0..1 : 32-row slice
    const int wn = wid >> 1;       // 0..3 : 32-col slice
    const int row0 = blockIdx.x * 64;

    const uint32_t sBase = (uint32_t)__cvta_generic_to_shared(&smem[0]);

    float acc[2][4][4];
    #pragma unroll
    for (int mi = 0; mi < 2; mi++)
        #pragma unroll
        for (int j = 0; j < 4; j++)
            #pragma unroll
            for (int q = 0; q < 4; q++) acc[mi][j][q] = 0.f;

    const int nk = K / 32;
    const int nchunks = (DUAL ? 2 : 1) * nk;

    float4 av[2];

    auto cp_b = [&](int c, int buf) {
        int s = (DUAL && c >= nk) ? 1 : 0;
        int kt = (s ? c - nk : c) * 32;
        const __nv_bfloat16* Bp = s ? B2 : B;
        #pragma unroll
        for (int p = 0; p < 2; p++)
            #pragma unroll
            for (int r = 0; r < 2; r++) {
                int idx = tid + r * 256;
                int kk = idx >> 4, h8 = idx & 15;
                uint32_t dst = sBase + SMB_BASE + buf * SMB_STR_BUF + p * SMB_STR_PART + kk * 272 + h8 * 16;
                const void* src = Bp + (size_t)p * K * 128 + (size_t)(kt + kk) * 128 + h8 * 8;
                asm volatile("cp.async.cg.shared.global [%0], [%1], 16;" :: "r"(dst), "l"(src));
            }
        asm volatile("cp.async.commit_group;" ::: "memory");
    };
    auto load_a = [&](int c) {
        int s = (DUAL && c >= nk) ? 1 : 0;
        int kt = (s ? c - nk : c) * 32;
        const float* Ap = s ? A2 : A;
        #pragma unroll
        for (int r = 0; r < 2; r++) {
            int idx = tid + r * 256;
            int m = idx >> 3, c4 = idx & 7;
            int row = row0 + m;
            av[r] = (row < M) ? *(const float4*)(Ap + (size_t)row * K + kt + c4 * 4)
                              : make_float4(0.f, 0.f, 0.f, 0.f);
        }
    };
    auto sts_a = [&](int buf) {
        #pragma unroll
        for (int r = 0; r < 2; r++) {
            int idx = tid + r * 256;
            int m = idx >> 3, c4 = idx & 7;
            float hx = bf_rn(av[r].x), hy = bf_rn(av[r].y);
            float hz = bf_rn(av[r].z), hw = bf_rn(av[r].w);
            uint2 hi, lo;
            hi.x = pack_bf16(hx, hy);
            hi.y = pack_bf16(hz, hw);
            lo.x = pack_bf16(av[r].x - hx, av[r].y - hy);
            lo.y = pack_bf16(av[r].z - hz, av[r].w - hw);
            int off = buf * SMA_STR_BUF + m * 80 + c4 * 8;
            *(uint2*)(&smem[off]) = hi;
            *(uint2*)(&smem[off + SMA_STR_PART]) = lo;
        }
    };

    cp_b(0, 0);
    load_a(0);
    sts_a(0);
    asm volatile("cp.async.wait_group 0;" ::: "memory");
    __syncthreads();

    for (int c = 0; c < nchunks; c++) {
        int buf = c & 1;
        if (c + 1 < nchunks) {
            cp_b(c + 1, buf ^ 1);
            load_a(c + 1);
        }

        uint32_t aHi = sBase + buf * SMA_STR_BUF;
        uint32_t aLo = aHi + SMA_STR_PART;
        uint32_t bHi = sBase + SMB_BASE + buf * SMB_STR_BUF;
        uint32_t bLo = bHi + SMB_STR_PART;

        #pragma unroll
        for (int ks = 0; ks < 2; ks++) {
            uint32_t aoff = (uint32_t)((wm * 32 + (lane & 15)) * 80 + ks * 32 + (lane >> 4) * 16);
            uint32_t ah[2][4], al[2][4];
            #pragma unroll
            for (int mi = 0; mi < 2; mi++) {
                ldm_x4(ah[mi][0], ah[mi][1], ah[mi][2], ah[mi][3], aHi + aoff + mi * 16 * 80);
                ldm_x4(al[mi][0], al[mi][1], al[mi][2], al[mi][3], aLo + aoff + mi * 16 * 80);
            }
            uint32_t bh[4][2], bl[4][2];
            #pragma unroll
            for (int p = 0; p < 2; p++) {
                int krow = ks * 16 + ((lane >> 3) & 1) * 8 + (lane & 7);
                int ncol = wn * 32 + p * 16 + (lane >> 4) * 8;
                uint32_t boff = (uint32_t)(krow * 272 + ncol * 2);
                ldm_x4_t(bh[2 * p][0], bh[2 * p][1], bh[2 * p + 1][0], bh[2 * p + 1][1], bHi + boff);
                ldm_x4_t(bl[2 * p][0], bl[2 * p][1], bl[2 * p + 1][0], bl[2 * p + 1][1], bLo + boff);
            }
            #pragma unroll
            for (int mi = 0; mi < 2; mi++)
                #pragma unroll
                for (int j = 0; j < 4; j++)
                    mma_bf16(acc[mi][j], ah[mi], bh[j][0], bh[j][1]);
            #pragma unroll
            for (int mi = 0; mi < 2; mi++)
                #pragma unroll
                for (int j = 0; j < 4; j++)
                    mma_bf16(acc[mi][j], ah[mi], bl[j][0], bl[j][1]);
            #pragma unroll
            for (int mi = 0; mi < 2; mi++)
                #pragma unroll
                for (int j = 0; j < 4; j++)
                    mma_bf16(acc[mi][j], al[mi], bh[j][0], bh[j][1]);
        }

        if (c + 1 < nchunks) {
            sts_a(buf ^ 1);
            asm volatile("cp.async.wait_group 0;" ::: "memory");
            __syncthreads();
        }
    }

    // ---- epilogue ----
    #pragma unroll
    for (int mi = 0; mi < 2; mi++) {
        int rl = row0 + wm * 32 + mi * 16 + (lane >> 2);
        int rh = rl + 8;
        float fl_l = 0.f, fl_h = 0.f;
        if (FLAGV) {
            if (rl < M) fl_l = (flags[rl] > 0) ? 1.f : 0.f;
            if (rh < M) fl_h = (flags[rh] > 0) ? 1.f : 0.f;
        }
        #pragma unroll
        for (int j = 0; j < 4; j++) {
            int col = wn * 32 + j * 8 + (lane & 3) * 2;
            float b0 = __ldg(&bias[col]), b1 = __ldg(&bias[col + 1]);
            float f0 = 0.f, f1 = 0.f;
            if (FLAGV) { f0 = __ldg(&flagvec[col]); f1 = __ldg(&flagvec[col + 1]); }
            float v0 = acc[mi][j][0] + b0;
            float v1 = acc[mi][j][1] + b1;
            float v2 = acc[mi][j][2] + b0;
            float v3 = acc[mi][j][3] + b1;
            if (FLAGV) { v0 += fl_l * f0; v1 += fl_l * f1; v2 += fl_h * f0; v3 += fl_h * f1; }
            if (RELU) {
                v0 = fmaxf(v0, 0.f); v1 = fmaxf(v1, 0.f);
                v2 = fmaxf(v2, 0.f); v3 = fmaxf(v3, 0.f);
            }
            if (rl < M) *(float2*)(C + (size_t)rl * 128 + col) = make_float2(v0, v1);
            if (rh < M) *(float2*)(C + (size_t)rh * 128 + col) = make_float2(v2, v3);
        }
    }
}

// ---------------- final edge-wise dot: one warp per supervision edge ----------------
__global__ void dot_kernel(const int* __restrict__ lu, const int* __restrict__ lm,
                           const float* __restrict__ U, const float* __restrict__ Mo,
                           float* __restrict__ out, int n) {
    int w = (blockIdx.x * blockDim.x + threadIdx.x) >> 5;
    int lane = threadIdx.x & 31;
    if (w >= n) return;
    int u = lu[w], m = lm[w];
    float4 a = *(const float4*)(U  + (size_t)u * Hc + lane * 4);
    float4 b = *(const float4*)(Mo + (size_t)m * Hc + lane * 4);
    float p = a.x * b.x + a.y * b.y + a.z * b.z + a.w * b.w;
    #pragma unroll
    for (int o = 16; o > 0; o >>= 1) p += __shfl_xor_sync(0xFFFFFFFFu, p, o);
    if (lane == 0) out[w] = p;
}

// ---------------- host launcher ----------------
extern "C" void kernel_launch(void* const* d_in, const int* in_sizes, int n_in,
                              void* d_out, int out_size) {
    const float* movie_feats = (const float*)d_in[0];
    const float* user_init   = (const float*)d_in[1];
    const int*   edge_src    = (const int*)d_in[2];
    const int*   edge_dst    = (const int*)d_in[3];
    const int*   lbl_user    = (const int*)d_in[4];
    const int*   lbl_movie   = (const int*)d_in[5];
    int wb = (in_sizes[6] == FDc * Hc) ? 6 : 7;
    const float* Wm     = (const float*)d_in[wb + 0];
    const float* bm     = (const float*)d_in[wb + 1];
    const float* Wl1_um = (const float*)d_in[wb + 2];
    const float* bl1_um = (const float*)d_in[wb + 3];
    const float* Wr1_um = (const float*)d_in[wb + 4];
    const float* Wl1_mu = (const float*)d_in[wb + 5];
    const float* bl1_mu = (const float*)d_in[wb + 6];
    const float* Wr1_mu = (const float*)d_in[wb + 7];
    const float* Wl2_um = (const float*)d_in[wb + 8];
    const float* bl2_um = (const float*)d_in[wb + 9];
    const float* Wr2_um = (const float*)d_in[wb + 10];
    const float* Wl2_mu = (const float*)d_in[wb + 11];
    const float* bl2_mu = (const float*)d_in[wb + 12];
    const float* Wr2_mu = (const float*)d_in[wb + 13];

    float* out = (float*)d_out;

    void *p_movie_x, *p_movie_h, *p_aggM, *p_user_h, *p_user_o, *p_aggU, *p_aggU2;
    void *p_cnt_m, *p_cnt_u, *p_off_m, *p_off_u, *p_pos_m, *p_pos_u;
    void *p_adj_m, *p_adj_u, *p_bsum_m, *p_bsum_u, *p_cvec, *p_bvec, *p_wpool;
    cudaGetSymbolAddress(&p_movie_x, g_movie_x);
    cudaGetSymbolAddress(&p_movie_h, g_movie_h);
    cudaGetSymbolAddress(&p_aggM,   g_aggM);
    cudaGetSymbolAddress(&p_user_h, g_user_h);
    cudaGetSymbolAddress(&p_user_o, g_user_o);
    cudaGetSymbolAddress(&p_aggU,   g_aggU);
    cudaGetSymbolAddress(&p_aggU2,  g_aggU2);
    cudaGetSymbolAddress(&p_cnt_m,  g_cnt_m);
    cudaGetSymbolAddress(&p_cnt_u,  g_cnt_u);
    cudaGetSymbolAddress(&p_off_m,  g_off_m);
    cudaGetSymbolAddress(&p_off_u,  g_off_u);
    cudaGetSymbolAddress(&p_pos_m,  g_pos_m);
    cudaGetSymbolAddress(&p_pos_u,  g_pos_u);
    cudaGetSymbolAddress(&p_adj_m,  g_adj_m);
    cudaGetSymbolAddress(&p_adj_u,  g_adj_u);
    cudaGetSymbolAddress(&p_bsum_m, g_bsum_m);
    cudaGetSymbolAddress(&p_bsum_u, g_bsum_u);
    cudaGetSymbolAddress(&p_cvec,   g_cvec);
    cudaGetSymbolAddress(&p_bvec,   g_bvec_u1);
    cudaGetSymbolAddress(&p_wpool,  g_wpool);

    float* movie_x = (float*)p_movie_x;
    float* movie_h = (float*)p_movie_h;
    float* aggM    = (float*)p_aggM;
    float* user_h  = (float*)p_user_h;
    float* user_o  = (float*)p_user_o;
    float* aggU    = (float*)p_aggU;
    float* aggU2   = (float*)p_aggU2;
    int* cnt_m = (int*)p_cnt_m; int* cnt_u = (int*)p_cnt_u;
    int* off_m = (int*)p_off_m; int* off_u = (int*)p_off_u;
    int* pos_m = (int*)p_pos_m; int* pos_u = (int*)p_pos_u;
    int* adj_m = (int*)p_adj_m; int* adj_u = (int*)p_adj_u;
    int* bsum_m = (int*)p_bsum_m; int* bsum_u = (int*)p_bsum_u;
    float* cvec = (float*)p_cvec; float* bvec_u1 = (float*)p_bvec;
    __nv_bfloat16* wpool = (__nv_bfloat16*)p_wpool;

    cudaFuncSetAttribute(gemm_mma2_kernel<false, false, false>, cudaFuncAttributeMaxDynamicSharedMemorySize, SM2_TOTAL);
    cudaFuncSetAttribute(gemm_mma2_kernel<true,  false, false>, cudaFuncAttributeMaxDynamicSharedMemorySize, SM2_TOTAL);
    cudaFuncSetAttribute(gemm_mma2_kernel<true,  false, true >, cudaFuncAttributeMaxDynamicSharedMemorySize, SM2_TOTAL);
    cudaFuncSetAttribute(gemm_mma2_kernel<false, true,  false>, cudaFuncAttributeMaxDynamicSharedMemorySize, SM2_TOTAL);

    const int nbM = (NMc + 1023) / 1024;
    const int nbU = (NUc + 1023) / 1024;
    const int gM = (NMc + 63) / 64;     // 1250
    const int gU = (NUc + 63) / 64;     // 3125

    cudaStream_t s1 = g_sr.s1;

    // ======== fork ========
    cudaEventRecord(g_sr.eFork, 0);
    cudaStreamWaitEvent(s1, g_sr.eFork, 0);

    // ---- s1: CSR build branch (L2/atomic-bound) ----
    zero_int_kernel<<<(NMc + 255) / 256, 256, 0, s1>>>(cnt_m, NMc);
    zero_int_kernel<<<(NUc + 255) / 256, 256, 0, s1>>>(cnt_u, NUc);
    hist_kernel<<<2048, 256, 0, s1>>>(edge_src, edge_dst, cnt_u, cnt_m, Ec);
    cudaEventRecord(g_sr.eHist, s1);
    scan_block_kernel<<<nbM, 1024, 0, s1>>>(cnt_m, off_m, bsum_m, NMc);
    scan_sums_kernel<<<1, 32, 0, s1>>>(bsum_m, nbM);
    scan_add_kernel<<<nbM, 1024, 0, s1>>>(off_m, bsum_m, NMc);
    scan_block_kernel<<<nbU, 1024, 0, s1>>>(cnt_u, off_u, bsum_u, NUc);
    scan_sums_kernel<<<1, 32, 0, s1>>>(bsum_u, nbU);
    scan_add_kernel<<<nbU, 1024, 0, s1>>>(off_u, bsum_u, NUc);
    copy_int_kernel<<<(NMc + 255) / 256, 256, 0, s1>>>(pos_m, off_m, NMc);
    copy_int_kernel<<<(NUc + 255) / 256, 256, 0, s1>>>(pos_u, off_u, NUc);
    place_kernel<<<2048, 256, 0, s1>>>(edge_src, edge_dst, pos_u, pos_m, adj_u, adj_m, Ec);
    cudaEventRecord(g_sr.eCsr, s1);

    // ---- s0: weight conversions + movie feature GEMM (tensor-bound) ----
    wconv_kernel<<<(FDc * Hc + 255) / 256, 256>>>(Wm,     wpool + OFF_WM,    FDc * Hc);
    wconv_kernel<<<(Hc * Hc + 255) / 256, 256>>>(Wl1_mu, wpool + OFF_WL1MU, Hc * Hc);
    wconv_kernel<<<(Hc * Hc + 255) / 256, 256>>>(Wr1_um, wpool + OFF_WR1UM, Hc * Hc);
    wconv_kernel<<<(Hc * Hc + 255) / 256, 256>>>(Wl2_um, wpool + OFF_WL2UM, Hc * Hc);
    wconv_kernel<<<(Hc * Hc + 255) / 256, 256>>>(Wr2_um, wpool + OFF_WR2UM, Hc * Hc);
    wconv_kernel<<<(Hc * Hc + 255) / 256, 256>>>(Wl2_mu, wpool + OFF_WL2MU, Hc * Hc);
    wconv_kernel<<<(Hc * Hc + 255) / 256, 256>>>(Wr2_mu, wpool + OFF_WR2MU, Hc * Hc);
    prevec_kernel<<<1, Hc>>>(user_init, Wl1_um, Wr1_mu, bl1_mu, cvec, bvec_u1);

    // movie_x = movie_feats @ Wm + bm
    gemm_mma2_kernel<false, false, false><<<gM, 256, SM2_TOTAL>>>(
        movie_feats, wpool + OFF_WM, FDc, nullptr, nullptr, bm, nullptr, nullptr, movie_x, NMc);
    cudaEventRecord(g_sr.eG1, 0);

    // s0: conv1 movie side (needs cnt_m from hist): movie_h = relu(movie_x@Wr1_um + bl1_um + flag*cvec)
    cudaStreamWaitEvent(0, g_sr.eHist, 0);
    gemm_mma2_kernel<true, false, true><<<gM, 256, SM2_TOTAL>>>(
        movie_x, wpool + OFF_WR1UM, Hc, nullptr, nullptr, bl1_um, cvec, cnt_m, movie_h, NMc);
    cudaEventRecord(g_sr.eMH, 0);

    // ---- s1: conv1 user aggregation (needs movie_x + CSR) then user_h GEMM ----
    cudaStreamWaitEvent(s1, g_sr.eG1, 0);
    agg_mean_kernel<<<(NUc * 32 + 255) / 256, 256, 0, s1>>>(off_u, adj_u, movie_x, aggU, NUc);
    gemm_mma2_kernel<true, false, false><<<gU, 256, SM2_TOTAL, s1>>>(
        aggU, wpool + OFF_WL1MU, Hc, nullptr, nullptr, bvec_u1, nullptr, nullptr, user_h, NUc);
    cudaEventRecord(g_sr.eUH, s1);

    // ---- s0: conv2 user aggregation (needs movie_h in-stream + CSR) ----
    cudaStreamWaitEvent(0, g_sr.eCsr, 0);
    agg_mean_kernel<<<(NUc * 32 + 255) / 256, 256>>>(off_u, adj_u, movie_h, aggU2, NUc);

    // ---- s1: conv2 movie side: aggM = mean(user_h); movie_o = aggM@Wl2_um + movie_h@Wr2_um + b ----
    agg_mean_kernel<<<(NMc * 32 + 255) / 256, 256, 0, s1>>>(off_m, adj_m, user_h, aggM, NMc);
    cudaStreamWaitEvent(s1, g_sr.eMH, 0);
    gemm_mma2_kernel<false, true, false><<<gM, 256, SM2_TOTAL, s1>>>(
        aggM, wpool + OFF_WL2UM, Hc, movie_h, wpool + OFF_WR2UM, bl2_um, nullptr, nullptr, movie_x, NMc);
    cudaEventRecord(g_sr.eMO, s1);

    // ---- s0: conv2 user side: user_o = aggU2@Wl2_mu + user_h@Wr2_mu + bl2_mu ----
    cudaStreamWaitEvent(0, g_sr.eUH, 0);
    gemm_mma2_kernel<false, true, false><<<gU, 256, SM2_TOTAL>>>(
        aggU2, wpool + OFF_WL2MU, Hc, user_h, wpool + OFF_WR2MU, bl2_mu, nullptr, nullptr, user_o, NUc);

    // ---- join + dot ----
    cudaStreamWaitEvent(0, g_sr.eMO, 0);
    dot_kernel<<<(ELc * 32 + 255) / 256, 256>>>(lbl_user, lbl_movie, user_o, movie_x, out, ELc);
}

// round 16
// speedup vs baseline: 1.1676x; 1.1243x over previous
#include <cuda_runtime.h>
#include <cuda_bf16.h>
#include <cuda_fp16.h>
#include <cstdint>

// Problem-size constants (fixed by the dataset)
#define NUc 200000
#define NMc 80000
#define Ec  2000000
#define ELc 500000
#define Hc  128
#define FDc 512

// ---------------- scratch (static device allocations; no cudaMalloc) ----------------
__device__ float g_movie_x[NMc * Hc];   // movie_x; later reused as movie_o
__device__ float g_movie_h[NMc * Hc];
__device__ float g_aggM  [NMc * Hc];
__device__ float g_user_h[NUc * Hc];
__device__ float g_user_o[NUc * Hc];
__device__ float g_aggU  [NUc * Hc];    // conv1 user aggregation
__device__ float g_aggU2 [NUc * Hc];    // conv2 user aggregation

__device__ int g_cnt_m[NMc];
__device__ int g_cnt_u[NUc];
__device__ int g_off_m[NMc + 1];
__device__ int g_off_u[NUc + 1];
__device__ int g_pos_m[NMc];
__device__ int g_pos_u[NUc];
__device__ int g_adj_m[Ec];             // user ids grouped by movie
__device__ int g_adj_u[Ec];             // movie ids grouped by user
__device__ int g_bsum_m[256];
__device__ int g_bsum_u[256];
__device__ float g_cvec[Hc];            // u0 @ Wl1_um
__device__ float g_bvec_u1[Hc];         // bl1_mu + u0 @ Wr1_mu

// bf16 hi/lo weight pool for the K=512 feature GEMM (3-term path)
__device__ __nv_bfloat16 g_wpool[2 * FDc * Hc];   // [hi | lo]

// single-fp16 weight pool for the six K=128 conv GEMMs (2-term path)
#define F16_WL1MU 0
#define F16_WR1UM 16384
#define F16_WL2UM 32768
#define F16_WR2UM 49152
#define F16_WL2MU 65536
#define F16_WR2MU 81920
__device__ __half g_wpool16[98304];

// ---------------- host-side stream/event resources (created pre-main) ----------------
struct StreamRes {
    cudaStream_t s1;
    cudaEvent_t eFork, eHist, eCsr, eG1, eMH, eUH, eMO;
    StreamRes() {
        cudaStreamCreateWithFlags(&s1, cudaStreamNonBlocking);
        cudaEventCreateWithFlags(&eFork, cudaEventDisableTiming);
        cudaEventCreateWithFlags(&eHist, cudaEventDisableTiming);
        cudaEventCreateWithFlags(&eCsr,  cudaEventDisableTiming);
        cudaEventCreateWithFlags(&eG1,   cudaEventDisableTiming);
        cudaEventCreateWithFlags(&eMH,   cudaEventDisableTiming);
        cudaEventCreateWithFlags(&eUH,   cudaEventDisableTiming);
        cudaEventCreateWithFlags(&eMO,   cudaEventDisableTiming);
    }
};
static StreamRes g_sr;

// ---------------- small utility kernels ----------------
__global__ void zero_int_kernel(int* p, int n) {
    int i = blockIdx.x * blockDim.x + threadIdx.x;
    if (i < n) p[i] = 0;
}
__global__ void copy_int_kernel(int* dst, const int* src, int n) {
    int i = blockIdx.x * blockDim.x + threadIdx.x;
    if (i < n) dst[i] = src[i];
}
__global__ void hist_kernel(const int* __restrict__ src, const int* __restrict__ dst,
                            int* cnt_u, int* cnt_m, int n) {
    for (int e = blockIdx.x * blockDim.x + threadIdx.x; e < n; e += gridDim.x * blockDim.x) {
        atomicAdd(&cnt_m[dst[e]], 1);
        atomicAdd(&cnt_u[src[e]], 1);
    }
}
__global__ void place_kernel(const int* __restrict__ src, const int* __restrict__ dst,
                             int* pos_u, int* pos_m, int* adj_u, int* adj_m, int n) {
    for (int e = blockIdx.x * blockDim.x + threadIdx.x; e < n; e += gridDim.x * blockDim.x) {
        int s = src[e], d = dst[e];
        int p = atomicAdd(&pos_m[d], 1);
        adj_m[p] = s;
        int q = atomicAdd(&pos_u[s], 1);
        adj_u[q] = d;
    }
}
__global__ void scan_block_kernel(const int* __restrict__ cnt, int* out, int* bsums, int n) {
    __shared__ int sh[1024];
    int tid = threadIdx.x;
    int i = blockIdx.x * 1024 + tid;
    int v = (i < n) ? cnt[i] : 0;
    sh[tid] = v;
    __syncthreads();
    #pragma unroll
    for (int off = 1; off < 1024; off <<= 1) {
        int t = (tid >= off) ? sh[tid - off] : 0;
        __syncthreads();
        sh[tid] += t;
        __syncthreads();
    }
    if (i < n) out[i + 1] = sh[tid];
    if (tid == 1023) bsums[blockIdx.x] = sh[1023];
}
__global__ void scan_sums_kernel(int* bsums, int nb) {
    if (threadIdx.x == 0 && blockIdx.x == 0) {
        int acc = 0;
        for (int b = 0; b < nb; b++) { int v = bsums[b]; bsums[b] = acc; acc += v; }
    }
}
__global__ void scan_add_kernel(int* out, const int* __restrict__ bsums, int n) {
    int i = blockIdx.x * 1024 + threadIdx.x;
    if (i < n) out[i + 1] += bsums[blockIdx.x];
    if (i == 0) out[0] = 0;
}
__global__ void prevec_kernel(const float* __restrict__ u0,
                              const float* __restrict__ Wl1um,
                              const float* __restrict__ Wr1mu,
                              const float* __restrict__ bl1mu,
                              float* cvec, float* bvec) {
    int j = threadIdx.x;
    float c = 0.f, r = 0.f;
    for (int k = 0; k < Hc; k++) {
        float u = u0[k];
        c += u * Wl1um[k * Hc + j];
        r += u * Wr1mu[k * Hc + j];
    }
    cvec[j] = c;
    bvec[j] = bl1mu[j] + r;
}

__device__ __forceinline__ float bf_rn(float v) {
    return __bfloat162float(__float2bfloat16_rn(v));
}
// bf16 hi/lo weight pre-conversion (feature GEMM)
__global__ void wconv_kernel(const float* __restrict__ W, __nv_bfloat16* out, int n) {
    int i = blockIdx.x * blockDim.x + threadIdx.x;
    if (i < n) {
        float w = W[i];
        float h = bf_rn(w);
        out[i] = __float2bfloat16_rn(h);
        out[n + i] = __float2bfloat16_rn(w - h);
    }
}
// single-fp16 weight pre-conversion (conv GEMMs)
__global__ void wconv16_kernel(const float* __restrict__ W, __half* out, int n) {
    int i = blockIdx.x * blockDim.x + threadIdx.x;
    if (i < n) out[i] = __float2half_rn(W[i]);
}

// ---------------- scatter-mean via CSR gather: one warp per destination node ----------------
__global__ void agg_mean_kernel(const int* __restrict__ off, const int* __restrict__ adj,
                                const float* __restrict__ X, float* __restrict__ out, int n) {
    int w = (blockIdx.x * blockDim.x + threadIdx.x) >> 5;
    int lane = threadIdx.x & 31;
    if (w >= n) return;
    int s = off[w], e = off[w + 1];
    float4 acc0 = make_float4(0.f, 0.f, 0.f, 0.f);
    float4 acc1 = make_float4(0.f, 0.f, 0.f, 0.f);
    int i = s;
    for (; i + 3 < e; i += 4) {
        int j0 = adj[i], j1 = adj[i + 1], j2 = adj[i + 2], j3 = adj[i + 3];
        float4 v0 = *(const float4*)(X + (size_t)j0 * Hc + lane * 4);
        float4 v1 = *(const float4*)(X + (size_t)j1 * Hc + lane * 4);
        float4 v2 = *(const float4*)(X + (size_t)j2 * Hc + lane * 4);
        float4 v3 = *(const float4*)(X + (size_t)j3 * Hc + lane * 4);
        acc0.x += v0.x + v1.x; acc0.y += v0.y + v1.y;
        acc0.z += v0.z + v1.z; acc0.w += v0.w + v1.w;
        acc1.x += v2.x + v3.x; acc1.y += v2.y + v3.y;
        acc1.z += v2.z + v3.z; acc1.w += v2.w + v3.w;
    }
    for (; i < e; i++) {
        int j = adj[i];
        float4 v = *(const float4*)(X + (size_t)j * Hc + lane * 4);
        acc0.x += v.x; acc0.y += v.y; acc0.z += v.z; acc0.w += v.w;
    }
    acc0.x += acc1.x; acc0.y += acc1.y; acc0.z += acc1.z; acc0.w += acc1.w;
    int cnt = e - s;
    float inv = 1.0f / (float)(cnt > 0 ? cnt : 1);
    acc0.x *= inv; acc0.y *= inv; acc0.z *= inv; acc0.w *= inv;
    *(float4*)(out + (size_t)w * Hc + lane * 4) = acc0;
}

// ---------------- mma.sync helpers ----------------
__device__ __forceinline__ void ldm_x4(uint32_t& r0, uint32_t& r1, uint32_t& r2, uint32_t& r3, uint32_t addr) {
    asm volatile("ldmatrix.sync.aligned.m8n8.x4.shared.b16 {%0,%1,%2,%3}, [%4];"
                 : "=r"(r0), "=r"(r1), "=r"(r2), "=r"(r3) : "r"(addr));
}
__device__ __forceinline__ void ldm_x4_t(uint32_t& r0, uint32_t& r1, uint32_t& r2, uint32_t& r3, uint32_t addr) {
    asm volatile("ldmatrix.sync.aligned.m8n8.x4.trans.shared.b16 {%0,%1,%2,%3}, [%4];"
                 : "=r"(r0), "=r"(r1), "=r"(r2), "=r"(r3) : "r"(addr));
}
__device__ __forceinline__ void mma_bf16(float* c, const uint32_t* a, uint32_t b0, uint32_t b1) {
    asm volatile(
        "mma.sync.aligned.m16n8k16.row.col.f32.bf16.bf16.f32 "
        "{%0,%1,%2,%3}, {%4,%5,%6,%7}, {%8,%9}, {%0,%1,%2,%3};"
        : "+f"(c[0]), "+f"(c[1]), "+f"(c[2]), "+f"(c[3])
        : "r"(a[0]), "r"(a[1]), "r"(a[2]), "r"(a[3]), "r"(b0), "r"(b1));
}
__device__ __forceinline__ void mma_f16(float* c, const uint32_t* a, uint32_t b0, uint32_t b1) {
    asm volatile(
        "mma.sync.aligned.m16n8k16.row.col.f32.f16.f16.f32 "
        "{%0,%1,%2,%3}, {%4,%5,%6,%7}, {%8,%9}, {%0,%1,%2,%3};"
        : "+f"(c[0]), "+f"(c[1]), "+f"(c[2]), "+f"(c[3])
        : "r"(a[0]), "r"(a[1]), "r"(a[2]), "r"(a[3]), "r"(b0), "r"(b1));
}
__device__ __forceinline__ uint32_t pack_bf16(float x, float y) {
    uint32_t r;
    asm("cvt.rn.bf16x2.f32 %0, %1, %2;" : "=r"(r) : "f"(y), "f"(x));
    return r;
}
__device__ __forceinline__ uint32_t pack_f16(float x, float y) {
    __half2 h = __floats2half2_rn(x, y);
    return *reinterpret_cast<uint32_t*>(&h);
}

// ---------------- 3-term split-bf16 GEMM (feature GEMM, K=512) ----------------
static constexpr int SMA_STR_BUF = 10240;
static constexpr int SMA_STR_PART = 5120;
static constexpr int SMB_BASE = 20480;
static constexpr int SMB_STR_BUF = 17408;
static constexpr int SMB_STR_PART = 8704;
static constexpr int SM2_TOTAL = 55296;

__global__ void __launch_bounds__(256) gemm_mma2_kernel(
    const float* __restrict__ A,  const __nv_bfloat16* __restrict__ B,  int K,
    const float* __restrict__ bias,
    float* __restrict__ C, int M)
{
    extern __shared__ __align__(16) char smem[];
    const int tid = threadIdx.x;
    const int lane = tid & 31;
    const int wid = tid >> 5;
    const int wm = wid & 1;
    const int wn = wid >> 1;
    const int row0 = blockIdx.x * 64;
    const uint32_t sBase = (uint32_t)__cvta_generic_to_shared(&smem[0]);

    float acc[2][4][4];
    #pragma unroll
    for (int mi = 0; mi < 2; mi++)
        #pragma unroll
        for (int j = 0; j < 4; j++)
            #pragma unroll
            for (int q = 0; q < 4; q++) acc[mi][j][q] = 0.f;

    const int nchunks = K / 32;
    float4 av[2];

    auto cp_b = [&](int c, int buf) {
        int kt = c * 32;
        #pragma unroll
        for (int p = 0; p < 2; p++)
            #pragma unroll
            for (int r = 0; r < 2; r++) {
                int idx = tid + r * 256;
                int kk = idx >> 4, h8 = idx & 15;
                uint32_t dst = sBase + SMB_BASE + buf * SMB_STR_BUF + p * SMB_STR_PART + kk * 272 + h8 * 16;
                const void* src = B + (size_t)p * K * 128 + (size_t)(kt + kk) * 128 + h8 * 8;
                asm volatile("cp.async.cg.shared.global [%0], [%1], 16;" :: "r"(dst), "l"(src));
            }
        asm volatile("cp.async.commit_group;" ::: "memory");
    };
    auto load_a = [&](int c) {
        int kt = c * 32;
        #pragma unroll
        for (int r = 0; r < 2; r++) {
            int idx = tid + r * 256;
            int m = idx >> 3, c4 = idx & 7;
            int row = row0 + m;
            av[r] = (row < M) ? *(const float4*)(A + (size_t)row * K + kt + c4 * 4)
                              : make_float4(0.f, 0.f, 0.f, 0.f);
        }
    };
    auto sts_a = [&](int buf) {
        #pragma unroll
        for (int r = 0; r < 2; r++) {
            int idx = tid + r * 256;
            int m = idx >> 3, c4 = idx & 7;
            float hx = bf_rn(av[r].x), hy = bf_rn(av[r].y);
            float hz = bf_rn(av[r].z), hw = bf_rn(av[r].w);
            uint2 hi, lo;
            hi.x = pack_bf16(hx, hy);
            hi.y = pack_bf16(hz, hw);
            lo.x = pack_bf16(av[r].x - hx, av[r].y - hy);
            lo.y = pack_bf16(av[r].z - hz, av[r].w - hw);
            int off = buf * SMA_STR_BUF + m * 80 + c4 * 8;
            *(uint2*)(&smem[off]) = hi;
            *(uint2*)(&smem[off + SMA_STR_PART]) = lo;
        }
    };

    cp_b(0, 0);
    load_a(0);
    sts_a(0);
    asm volatile("cp.async.wait_group 0;" ::: "memory");
    __syncthreads();

    for (int c = 0; c < nchunks; c++) {
        int buf = c & 1;
        if (c + 1 < nchunks) {
            cp_b(c + 1, buf ^ 1);
            load_a(c + 1);
        }
        uint32_t aHi = sBase + buf * SMA_STR_BUF;
        uint32_t aLo = aHi + SMA_STR_PART;
        uint32_t bHi = sBase + SMB_BASE + buf * SMB_STR_BUF;
        uint32_t bLo = bHi + SMB_STR_PART;

        #pragma unroll
        for (int ks = 0; ks < 2; ks++) {
            uint32_t aoff = (uint32_t)((wm * 32 + (lane & 15)) * 80 + ks * 32 + (lane >> 4) * 16);
            uint32_t ah[2][4], al[2][4];
            #pragma unroll
            for (int mi = 0; mi < 2; mi++) {
                ldm_x4(ah[mi][0], ah[mi][1], ah[mi][2], ah[mi][3], aHi + aoff + mi * 16 * 80);
                ldm_x4(al[mi][0], al[mi][1], al[mi][2], al[mi][3], aLo + aoff + mi * 16 * 80);
            }
            uint32_t bh[4][2], bl[4][2];
            #pragma unroll
            for (int p = 0; p < 2; p++) {
                int krow = ks * 16 + ((lane >> 3) & 1) * 8 + (lane & 7);
                int ncol = wn * 32 + p * 16 + (lane >> 4) * 8;
                uint32_t boff = (uint32_t)(krow * 272 + ncol * 2);
                ldm_x4_t(bh[2 * p][0], bh[2 * p][1], bh[2 * p + 1][0], bh[2 * p + 1][1], bHi + boff);
                ldm_x4_t(bl[2 * p][0], bl[2 * p][1], bl[2 * p + 1][0], bl[2 * p + 1][1], bLo + boff);
            }
            #pragma unroll
            for (int mi = 0; mi < 2; mi++)
                #pragma unroll
                for (int j = 0; j < 4; j++)
                    mma_bf16(acc[mi][j], ah[mi], bh[j][0], bh[j][1]);
            #pragma unroll
            for (int mi = 0; mi < 2; mi++)
                #pragma unroll
                for (int j = 0; j < 4; j++)
                    mma_bf16(acc[mi][j], ah[mi], bl[j][0], bl[j][1]);
            #pragma unroll
            for (int mi = 0; mi < 2; mi++)
                #pragma unroll
                for (int j = 0; j < 4; j++)
                    mma_bf16(acc[mi][j], al[mi], bh[j][0], bh[j][1]);
        }

        if (c + 1 < nchunks) {
            sts_a(buf ^ 1);
            asm volatile("cp.async.wait_group 0;" ::: "memory");
            __syncthreads();
        }
    }

    #pragma unroll
    for (int mi = 0; mi < 2; mi++) {
        int rl = row0 + wm * 32 + mi * 16 + (lane >> 2);
        int rh = rl + 8;
        #pragma unroll
        for (int j = 0; j < 4; j++) {
            int col = wn * 32 + j * 8 + (lane & 3) * 2;
            float b0 = __ldg(&bias[col]), b1 = __ldg(&bias[col + 1]);
            float v0 = acc[mi][j][0] + b0;
            float v1 = acc[mi][j][1] + b1;
            float v2 = acc[mi][j][2] + b0;
            float v3 = acc[mi][j][3] + b1;
            if (rl < M) *(float2*)(C + (size_t)rl * 128 + col) = make_float2(v0, v1);
            if (rh < M) *(float2*)(C + (size_t)rh * 128 + col) = make_float2(v2, v3);
        }
    }
}

// ---------------- 2-term split-fp16 GEMM (conv GEMMs, K=128) ----------------
// C = epi( A@W [+ A2@W2] + bias [+ flag*flagvec] ), A split fp16 hi/lo, W single fp16.
static constexpr int SF_A_BUF = 10240;   // 2 parts x 5120
static constexpr int SF_A_PART = 5120;
static constexpr int SF_B_BASE = 20480;
static constexpr int SF_B_BUF = 8704;    // single part, 32 rows x 272B
static constexpr int SF_TOTAL = 37888;

template<bool RELU, bool DUAL, bool FLAGV>
__global__ void __launch_bounds__(256) gemm_f16_kernel(
    const float* __restrict__ A,  const __half* __restrict__ B,
    const float* __restrict__ A2, const __half* __restrict__ B2,
    const float* __restrict__ bias,
    const float* __restrict__ flagvec, const int* __restrict__ flags,
    float* __restrict__ C, int M)
{
    extern __shared__ __align__(16) char smem[];
    const int tid = threadIdx.x;
    const int lane = tid & 31;
    const int wid = tid >> 5;
    const int wm = wid & 1;
    const int wn = wid >> 1;
    const int row0 = blockIdx.x * 64;
    const uint32_t sBase = (uint32_t)__cvta_generic_to_shared(&smem[0]);
    const int K = 128;

    float acc[2][4][4];
    #pragma unroll
    for (int mi = 0; mi < 2; mi++)
        #pragma unroll
        for (int j = 0; j < 4; j++)
            #pragma unroll
            for (int q = 0; q < 4; q++) acc[mi][j][q] = 0.f;

    const int nk = 4;                       // K/32
    const int nchunks = (DUAL ? 2 : 1) * nk;
    float4 av[2];

    auto cp_b = [&](int c, int buf) {
        int s = (DUAL && c >= nk) ? 1 : 0;
        int kt = (s ? c - nk : c) * 32;
        const __half* Bp = s ? B2 : B;
        #pragma unroll
        for (int r = 0; r < 2; r++) {
            int idx = tid + r * 256;
            int kk = idx >> 4, h8 = idx & 15;
            uint32_t dst = sBase + SF_B_BASE + buf * SF_B_BUF + kk * 272 + h8 * 16;
            const void* src = Bp + (size_t)(kt + kk) * 128 + h8 * 8;
            asm volatile("cp.async.cg.shared.global [%0], [%1], 16;" :: "r"(dst), "l"(src));
        }
        asm volatile("cp.async.commit_group;" ::: "memory");
    };
    auto load_a = [&](int c) {
        int s = (DUAL && c >= nk) ? 1 : 0;
        int kt = (s ? c - nk : c) * 32;
        const float* Ap = s ? A2 : A;
        #pragma unroll
        for (int r = 0; r < 2; r++) {
            int idx = tid + r * 256;
            int m = idx >> 3, c4 = idx & 7;
            int row = row0 + m;
            av[r] = (row < M) ? *(const float4*)(Ap + (size_t)row * K + kt + c4 * 4)
                              : make_float4(0.f, 0.f, 0.f, 0.f);
        }
    };
    auto sts_a = [&](int buf) {
        #pragma unroll
        for (int r = 0; r < 2; r++) {
            int idx = tid + r * 256;
            int m = idx >> 3, c4 = idx & 7;
            float hx = __half2float(__float2half_rn(av[r].x));
            float hy = __half2float(__float2half_rn(av[r].y));
            float hz = __half2float(__float2half_rn(av[r].z));
            float hw = __half2float(__float2half_rn(av[r].w));
            uint2 hi, lo;
            hi.x = pack_f16(hx, hy);
            hi.y = pack_f16(hz, hw);
            lo.x = pack_f16(av[r].x - hx, av[r].y - hy);
            lo.y = pack_f16(av[r].z - hz, av[r].w - hw);
            int off = buf * SF_A_BUF + m * 80 + c4 * 8;
            *(uint2*)(&smem[off]) = hi;
            *(uint2*)(&smem[off + SF_A_PART]) = lo;
        }
    };

    cp_b(0, 0);
    load_a(0);
    sts_a(0);
    asm volatile("cp.async.wait_group 0;" ::: "memory");
    __syncthreads();

    for (int c = 0; c < nchunks; c++) {
        int buf = c & 1;
        if (c + 1 < nchunks) {
            cp_b(c + 1, buf ^ 1);
            load_a(c + 1);
        }
        uint32_t aHi = sBase + buf * SF_A_BUF;
        uint32_t aLo = aHi + SF_A_PART;
        uint32_t bB = sBase + SF_B_BASE + buf * SF_B_BUF;

        #pragma unroll
        for (int ks = 0; ks < 2; ks++) {
            uint32_t aoff = (uint32_t)((wm * 32 + (lane & 15)) * 80 + ks * 32 + (lane >> 4) * 16);
            uint32_t ah[2][4], al[2][4];
            #pragma unroll
            for (int mi = 0; mi < 2; mi++) {
                ldm_x4(ah[mi][0], ah[mi][1], ah[mi][2], ah[mi][3], aHi + aoff + mi * 16 * 80);
                ldm_x4(al[mi][0], al[mi][1], al[mi][2], al[mi][3], aLo + aoff + mi * 16 * 80);
            }
            uint32_t bh[4][2];
            #pragma unroll
            for (int p = 0; p < 2; p++) {
                int krow = ks * 16 + ((lane >> 3) & 1) * 8 + (lane & 7);
                int ncol = wn * 32 + p * 16 + (lane >> 4) * 8;
                uint32_t boff = (uint32_t)(krow * 272 + ncol * 2);
                ldm_x4_t(bh[2 * p][0], bh[2 * p][1], bh[2 * p + 1][0], bh[2 * p + 1][1], bB + boff);
            }
            #pragma unroll
            for (int mi = 0; mi < 2; mi++)
                #pragma unroll
                for (int j = 0; j < 4; j++)
                    mma_f16(acc[mi][j], ah[mi], bh[j][0], bh[j][1]);
            #pragma unroll
            for (int mi = 0; mi < 2; mi++)
                #pragma unroll
                for (int j = 0; j < 4; j++)
                    mma_f16(acc[mi][j], al[mi], bh[j][0], bh[j][1]);
        }

        if (c + 1 < nchunks) {
            sts_a(buf ^ 1);
            asm volatile("cp.async.wait_group 0;" ::: "memory");
            __syncthreads();
        }
    }

    #pragma unroll
    for (int mi = 0; mi < 2; mi++) {
        int rl = row0 + wm * 32 + mi * 16 + (lane >> 2);
        int rh = rl + 8;
        float fl_l = 0.f, fl_h = 0.f;
        if (FLAGV) {
            if (rl < M) fl_l = (flags[rl] > 0) ? 1.f : 0.f;
            if (rh < M) fl_h = (flags[rh] > 0) ? 1.f : 0.f;
        }
        #pragma unroll
        for (int j = 0; j < 4; j++) {
            int col = wn * 32 + j * 8 + (lane & 3) * 2;
            float b0 = __ldg(&bias[col]), b1 = __ldg(&bias[col + 1]);
            float f0 = 0.f, f1 = 0.f;
            if (FLAGV) { f0 = __ldg(&flagvec[col]); f1 = __ldg(&flagvec[col + 1]); }
            float v0 = acc[mi][j][0] + b0;
            float v1 = acc[mi][j][1] + b1;
            float v2 = acc[mi][j][2] + b0;
            float v3 = acc[mi][j][3] + b1;
            if (FLAGV) { v0 += fl_l * f0; v1 += fl_l * f1; v2 += fl_h * f0; v3 += fl_h * f1; }
            if (RELU) {
                v0 = fmaxf(v0, 0.f); v1 = fmaxf(v1, 0.f);
                v2 = fmaxf(v2, 0.f); v3 = fmaxf(v3, 0.f);
            }
            if (rl < M) *(float2*)(C + (size_t)rl * 128 + col) = make_float2(v0, v1);
            if (rh < M) *(float2*)(C + (size_t)rh * 128 + col) = make_float2(v2, v3);
        }
    }
}

// ---------------- final edge-wise dot: one warp per supervision edge ----------------
__global__ void dot_kernel(const int* __restrict__ lu, const int* __restrict__ lm,
                           const float* __restrict__ U, const float* __restrict__ Mo,
                           float* __restrict__ out, int n) {
    int w = (blockIdx.x * blockDim.x + threadIdx.x) >> 5;
    int lane = threadIdx.x & 31;
    if (w >= n) return;
    int u = lu[w], m = lm[w];
    float4 a = *(const float4*)(U  + (size_t)u * Hc + lane * 4);
    float4 b = *(const float4*)(Mo + (size_t)m * Hc + lane * 4);
    float p = a.x * b.x + a.y * b.y + a.z * b.z + a.w * b.w;
    #pragma unroll
    for (int o = 16; o > 0; o >>= 1) p += __shfl_xor_sync(0xFFFFFFFFu, p, o);
    if (lane == 0) out[w] = p;
}

// ---------------- host launcher ----------------
extern "C" void kernel_launch(void* const* d_in, const int* in_sizes, int n_in,
                              void* d_out, int out_size) {
    const float* movie_feats = (const float*)d_in[0];
    const float* user_init   = (const float*)d_in[1];
    const int*   edge_src    = (const int*)d_in[2];
    const int*   edge_dst    = (const int*)d_in[3];
    const int*   lbl_user    = (const int*)d_in[4];
    const int*   lbl_movie   = (const int*)d_in[5];
    int wb = (in_sizes[6] == FDc * Hc) ? 6 : 7;
    const float* Wm     = (const float*)d_in[wb + 0];
    const float* bm     = (const float*)d_in[wb + 1];
    const float* Wl1_um = (const float*)d_in[wb + 2];
    const float* bl1_um = (const float*)d_in[wb + 3];
    const float* Wr1_um = (const float*)d_in[wb + 4];
    const float* Wl1_mu = (const float*)d_in[wb + 5];
    const float* bl1_mu = (const float*)d_in[wb + 6];
    const float* Wr1_mu = (const float*)d_in[wb + 7];
    const float* Wl2_um = (const float*)d_in[wb + 8];
    const float* bl2_um = (const float*)d_in[wb + 9];
    const float* Wr2_um = (const float*)d_in[wb + 10];
    const float* Wl2_mu = (const float*)d_in[wb + 11];
    const float* bl2_mu = (const float*)d_in[wb + 12];
    const float* Wr2_mu = (const float*)d_in[wb + 13];

    float* out = (float*)d_out;

    void *p_movie_x, *p_movie_h, *p_aggM, *p_user_h, *p_user_o, *p_aggU, *p_aggU2;
    void *p_cnt_m, *p_cnt_u, *p_off_m, *p_off_u, *p_pos_m, *p_pos_u;
    void *p_adj_m, *p_adj_u, *p_bsum_m, *p_bsum_u, *p_cvec, *p_bvec, *p_wpool, *p_wpool16;
    cudaGetSymbolAddress(&p_movie_x, g_movie_x);
    cudaGetSymbolAddress(&p_movie_h, g_movie_h);
    cudaGetSymbolAddress(&p_aggM,   g_aggM);
    cudaGetSymbolAddress(&p_user_h, g_user_h);
    cudaGetSymbolAddress(&p_user_o, g_user_o);
    cudaGetSymbolAddress(&p_aggU,   g_aggU);
    cudaGetSymbolAddress(&p_aggU2,  g_aggU2);
    cudaGetSymbolAddress(&p_cnt_m,  g_cnt_m);
    cudaGetSymbolAddress(&p_cnt_u,  g_cnt_u);
    cudaGetSymbolAddress(&p_off_m,  g_off_m);
    cudaGetSymbolAddress(&p_off_u,  g_off_u);
    cudaGetSymbolAddress(&p_pos_m,  g_pos_m);
    cudaGetSymbolAddress(&p_pos_u,  g_pos_u);
    cudaGetSymbolAddress(&p_adj_m,  g_adj_m);
    cudaGetSymbolAddress(&p_adj_u,  g_adj_u);
    cudaGetSymbolAddress(&p_bsum_m, g_bsum_m);
    cudaGetSymbolAddress(&p_bsum_u, g_bsum_u);
    cudaGetSymbolAddress(&p_cvec,   g_cvec);
    cudaGetSymbolAddress(&p_bvec,   g_bvec_u1);
    cudaGetSymbolAddress(&p_wpool,  g_wpool);
    cudaGetSymbolAddress(&p_wpool16, g_wpool16);

    float* movie_x = (float*)p_movie_x;
    float* movie_h = (float*)p_movie_h;
    float* aggM    = (float*)p_aggM;
    float* user_h  = (float*)p_user_h;
    float* user_o  = (float*)p_user_o;
    float* aggU    = (float*)p_aggU;
    float* aggU2   = (float*)p_aggU2;
    int* cnt_m = (int*)p_cnt_m; int* cnt_u = (int*)p_cnt_u;
    int* off_m = (int*)p_off_m; int* off_u = (int*)p_off_u;
    int* pos_m = (int*)p_pos_m; int* pos_u = (int*)p_pos_u;
    int* adj_m = (int*)p_adj_m; int* adj_u = (int*)p_adj_u;
    int* bsum_m = (int*)p_bsum_m; int* bsum_u = (int*)p_bsum_u;
    float* cvec = (float*)p_cvec; float* bvec_u1 = (float*)p_bvec;
    __nv_bfloat16* wpool = (__nv_bfloat16*)p_wpool;
    __half* wpool16 = (__half*)p_wpool16;

    cudaFuncSetAttribute(gemm_mma2_kernel, cudaFuncAttributeMaxDynamicSharedMemorySize, SM2_TOTAL);
    cudaFuncSetAttribute(gemm_f16_kernel<true,  false, false>, cudaFuncAttributeMaxDynamicSharedMemorySize, SF_TOTAL);
    cudaFuncSetAttribute(gemm_f16_kernel<true,  false, true >, cudaFuncAttributeMaxDynamicSharedMemorySize, SF_TOTAL);
    cudaFuncSetAttribute(gemm_f16_kernel<false, true,  false>, cudaFuncAttributeMaxDynamicSharedMemorySize, SF_TOTAL);

    const int nbM = (NMc + 1023) / 1024;
    const int nbU = (NUc + 1023) / 1024;
    const int gM = (NMc + 63) / 64;     // 1250
    const int gU = (NUc + 63) / 64;     // 3125

    cudaStream_t s1 = g_sr.s1;

    // ======== fork ========
    cudaEventRecord(g_sr.eFork, 0);
    cudaStreamWaitEvent(s1, g_sr.eFork, 0);

    // ---- s1: CSR build branch (L2/atomic-bound) ----
    zero_int_kernel<<<(NMc + 255) / 256, 256, 0, s1>>>(cnt_m, NMc);
    zero_int_kernel<<<(NUc + 255) / 256, 256, 0, s1>>>(cnt_u, NUc);
    hist_kernel<<<2048, 256, 0, s1>>>(edge_src, edge_dst, cnt_u, cnt_m, Ec);
    cudaEventRecord(g_sr.eHist, s1);
    scan_block_kernel<<<nbM, 1024, 0, s1>>>(cnt_m, off_m, bsum_m, NMc);
    scan_sums_kernel<<<1, 32, 0, s1>>>(bsum_m, nbM);
    scan_add_kernel<<<nbM, 1024, 0, s1>>>(off_m, bsum_m, NMc);
    scan_block_kernel<<<nbU, 1024, 0, s1>>>(cnt_u, off_u, bsum_u, NUc);
    scan_sums_kernel<<<1, 32, 0, s1>>>(bsum_u, nbU);
    scan_add_kernel<<<nbU, 1024, 0, s1>>>(off_u, bsum_u, NUc);
    copy_int_kernel<<<(NMc + 255) / 256, 256, 0, s1>>>(pos_m, off_m, NMc);
    copy_int_kernel<<<(NUc + 255) / 256, 256, 0, s1>>>(pos_u, off_u, NUc);
    place_kernel<<<2048, 256, 0, s1>>>(edge_src, edge_dst, pos_u, pos_m, adj_u, adj_m, Ec);
    cudaEventRecord(g_sr.eCsr, s1);

    // ---- s0: weight conversions + movie feature GEMM (tensor-bound) ----
    wconv_kernel<<<(FDc * Hc + 255) / 256, 256>>>(Wm, wpool, FDc * Hc);
    wconv16_kernel<<<(Hc * Hc + 255) / 256, 256>>>(Wl1_mu, wpool16 + F16_WL1MU, Hc * Hc);
    wconv16_kernel<<<(Hc * Hc + 255) / 256, 256>>>(Wr1_um, wpool16 + F16_WR1UM, Hc * Hc);
    wconv16_kernel<<<(Hc * Hc + 255) / 256, 256>>>(Wl2_um, wpool16 + F16_WL2UM, Hc * Hc);
    wconv16_kernel<<<(Hc * Hc + 255) / 256, 256>>>(Wr2_um, wpool16 + F16_WR2UM, Hc * Hc);
    wconv16_kernel<<<(Hc * Hc + 255) / 256, 256>>>(Wl2_mu, wpool16 + F16_WL2MU, Hc * Hc);
    wconv16_kernel<<<(Hc * Hc + 255) / 256, 256>>>(Wr2_mu, wpool16 + F16_WR2MU, Hc * Hc);
    prevec_kernel<<<1, Hc>>>(user_init, Wl1_um, Wr1_mu, bl1_mu, cvec, bvec_u1);

    // movie_x = movie_feats @ Wm + bm  (3-term bf16)
    gemm_mma2_kernel<<<gM, 256, SM2_TOTAL>>>(movie_feats, wpool, FDc, bm, movie_x, NMc);
    cudaEventRecord(g_sr.eG1, 0);

    // s0: conv1 movie side: movie_h = relu(movie_x@Wr1_um + bl1_um + flag*cvec)  (fp16 2-term)
    cudaStreamWaitEvent(0, g_sr.eHist, 0);
    gemm_f16_kernel<true, false, true><<<gM, 256, SF_TOTAL>>>(
        movie_x, wpool16 + F16_WR1UM, nullptr, nullptr, bl1_um, cvec, cnt_m, movie_h, NMc);
    cudaEventRecord(g_sr.eMH, 0);

    // ---- s1: conv1 user aggregation then user_h GEMM ----
    cudaStreamWaitEvent(s1, g_sr.eG1, 0);
    agg_mean_kernel<<<(NUc * 32 + 255) / 256, 256, 0, s1>>>(off_u, adj_u, movie_x, aggU, NUc);
    gemm_f16_kernel<true, false, false><<<gU, 256, SF_TOTAL, s1>>>(
        aggU, wpool16 + F16_WL1MU, nullptr, nullptr, bvec_u1, nullptr, nullptr, user_h, NUc);
    cudaEventRecord(g_sr.eUH, s1);

    // ---- s0: conv2 user aggregation ----
    cudaStreamWaitEvent(0, g_sr.eCsr, 0);
    agg_mean_kernel<<<(NUc * 32 + 255) / 256, 256>>>(off_u, adj_u, movie_h, aggU2, NUc);

    // ---- s1: conv2 movie side ----
    agg_mean_kernel<<<(NMc * 32 + 255) / 256, 256, 0, s1>>>(off_m, adj_m, user_h, aggM, NMc);
    cudaStreamWaitEvent(s1, g_sr.eMH, 0);
    gemm_f16_kernel<false, true, false><<<gM, 256, SF_TOTAL, s1>>>(
        aggM, wpool16 + F16_WL2UM, movie_h, wpool16 + F16_WR2UM, bl2_um, nullptr, nullptr, movie_x, NMc);
    cudaEventRecord(g_sr.eMO, s1);

    // ---- s0: conv2 user side ----
    cudaStreamWaitEvent(0, g_sr.eUH, 0);
    gemm_f16_kernel<false, true, false><<<gU, 256, SF_TOTAL>>>(
        aggU2, wpool16 + F16_WL2MU, user_h, wpool16 + F16_WR2MU, bl2_mu, nullptr, nullptr, user_o, NUc);

    // ---- join + dot ----
    cudaStreamWaitEvent(0, g_sr.eMO, 0);
    dot_kernel<<<(ELc * 32 + 255) / 256, 256>>>(lbl_user, lbl_movie, user_o, movie_x, out, ELc);
}